// round 1
// baseline (speedup 1.0000x reference)
#include <cuda_runtime.h>
#include <math.h>

#define D_MODEL 1024
#define N_HEADS 16
#define D_HEAD  64
#define B_SZ    4
#define SEQ     2048
#define M_ROWS  (B_SZ * SEQ)   // 8192

// Scratch buffers (allocation-free rule: __device__ globals)
__device__ float g_q [M_ROWS * D_MODEL];
__device__ float g_k [M_ROWS * D_MODEL];
__device__ float g_v [M_ROWS * D_MODEL];
__device__ float g_ao[M_ROWS * D_MODEL];

// ---------------------------------------------------------------------------
// NT GEMM: C[m,n] = sum_k A[m,k] * B[n,k]   (A:[M,K] row-major, B:[N,K] row-major)
// BM=BN=128, BK=16, 256 threads, 8x8 per thread.
// ---------------------------------------------------------------------------
#define BM 128
#define BN 128
#define BK 16
#define AP (BM + 4)   // padded pitch (132 floats = 528B, 16B-aligned rows)

__global__ __launch_bounds__(256, 2)
void gemm_nt(const float* __restrict__ A, const float* __restrict__ Bw,
             float* __restrict__ C, int Mdim, int Ndim, int Kdim)
{
    __shared__ __align__(16) float As[BK][AP];
    __shared__ __align__(16) float Bs[BK][AP];

    const int tid = threadIdx.x;
    const int tx = tid & 15;        // 0..15
    const int ty = tid >> 4;        // 0..15
    const int m0 = blockIdx.y * BM;
    const int n0 = blockIdx.x * BN;

    const float* Aptr = A  + (size_t)m0 * Kdim;
    const float* Bptr = Bw + (size_t)n0 * Kdim;

    float acc[8][8];
#pragma unroll
    for (int i = 0; i < 8; i++)
#pragma unroll
        for (int j = 0; j < 8; j++) acc[i][j] = 0.f;

    for (int k0 = 0; k0 < Kdim; k0 += BK) {
        // 128 rows x 16 k = 512 float4 per tile; 2 per thread, per operand
#pragma unroll
        for (int it = 0; it < 2; it++) {
            int idx = tid + it * 256;
            int r  = idx >> 2;      // row in tile (0..127)
            int c4 = idx & 3;       // which float4 of the 16-wide k slab
            float4 va = *(const float4*)(Aptr + (size_t)r * Kdim + k0 + c4 * 4);
            As[c4*4+0][r] = va.x; As[c4*4+1][r] = va.y;
            As[c4*4+2][r] = va.z; As[c4*4+3][r] = va.w;
            float4 vb = *(const float4*)(Bptr + (size_t)r * Kdim + k0 + c4 * 4);
            Bs[c4*4+0][r] = vb.x; Bs[c4*4+1][r] = vb.y;
            Bs[c4*4+2][r] = vb.z; Bs[c4*4+3][r] = vb.w;
        }
        __syncthreads();

#pragma unroll
        for (int k = 0; k < BK; k++) {
            float a[8], b[8];
            *(float4*)&a[0] = *(const float4*)&As[k][ty * 8];
            *(float4*)&a[4] = *(const float4*)&As[k][ty * 8 + 4];
            *(float4*)&b[0] = *(const float4*)&Bs[k][tx * 8];
            *(float4*)&b[4] = *(const float4*)&Bs[k][tx * 8 + 4];
#pragma unroll
            for (int i = 0; i < 8; i++)
#pragma unroll
                for (int j = 0; j < 8; j++)
                    acc[i][j] += a[i] * b[j];
        }
        __syncthreads();
    }

#pragma unroll
    for (int i = 0; i < 8; i++) {
        int m = m0 + ty * 8 + i;
#pragma unroll
        for (int j = 0; j < 8; j += 4) {
            float4 v = make_float4(acc[i][j], acc[i][j+1], acc[i][j+2], acc[i][j+3]);
            *(float4*)(C + (size_t)m * Ndim + n0 + tx * 8 + j) = v;
        }
    }
}

// ---------------------------------------------------------------------------
// Flash attention (fp32, causal). One CTA = (q-tile of 128 rows, head, batch).
// Q/K stored d-major (transposed) in smem; P staged via smem for the PV pass.
// ---------------------------------------------------------------------------
#define BQ  128
#define BKV 128
#define TP  (BQ + 4)       // 132: pitch of Qt/Kt rows ([d][q])
#define VP  (D_HEAD + 4)   // 68:  pitch of Vs rows ([j][d])
#define PSP (BKV + 4)      // 132: pitch of Ps rows ([q][j])

#define SM_QT   0
#define SM_KT   (D_HEAD * TP)                 // 8448
#define SM_VS   (SM_KT + D_HEAD * TP)         // 16896
#define SM_PS   (SM_VS + BKV * VP)            // 25600
#define SM_FLOATS (SM_PS + BQ * PSP)          // 42496
#define SMEM_BYTES (SM_FLOATS * 4)            // 169984

__global__ __launch_bounds__(256, 1)
void flash_attn_causal()
{
    extern __shared__ __align__(16) float sm[];
    float* Qt = sm + SM_QT;
    float* Kt = sm + SM_KT;
    float* Vs = sm + SM_VS;
    float* Ps = sm + SM_PS;

    const int tid = threadIdx.x;
    const int tx = tid & 15;
    const int ty = tid >> 4;
    const int qt = blockIdx.x;
    const int h  = blockIdx.y;
    const int b  = blockIdx.z;
    const int q0 = qt * BQ;

    const float scale = 0.125f;  // 1/sqrt(64)

    // Load Q tile (128 x 64), transposed into Qt[d][q], pre-scaled.
    const float* Qg = g_q + ((size_t)(b * SEQ + q0)) * D_MODEL + h * D_HEAD;
#pragma unroll
    for (int it = 0; it < 8; it++) {
        int idx = tid + it * 256;          // 0..2047 float4s
        int r  = idx >> 4;                 // q row 0..127
        int d4 = idx & 15;                 // float4 index within 64-d row
        float4 v = *(const float4*)(Qg + (size_t)r * D_MODEL + d4 * 4);
        Qt[(d4*4+0) * TP + r] = v.x * scale;
        Qt[(d4*4+1) * TP + r] = v.y * scale;
        Qt[(d4*4+2) * TP + r] = v.z * scale;
        Qt[(d4*4+3) * TP + r] = v.w * scale;
    }

    float m_i[8], l_i[8], o[8][4];
#pragma unroll
    for (int i = 0; i < 8; i++) {
        m_i[i] = -1e30f; l_i[i] = 0.f;
        o[i][0] = o[i][1] = o[i][2] = o[i][3] = 0.f;
    }

    const int ntiles = qt + 1;
    for (int t = 0; t < ntiles; t++) {
        const int j0 = t * BKV;
        const float* Kg = g_k + ((size_t)(b * SEQ + j0)) * D_MODEL + h * D_HEAD;
        const float* Vg = g_v + ((size_t)(b * SEQ + j0)) * D_MODEL + h * D_HEAD;
#pragma unroll
        for (int it = 0; it < 8; it++) {
            int idx = tid + it * 256;
            int r  = idx >> 4;
            int d4 = idx & 15;
            float4 kv = *(const float4*)(Kg + (size_t)r * D_MODEL + d4 * 4);
            Kt[(d4*4+0) * TP + r] = kv.x;
            Kt[(d4*4+1) * TP + r] = kv.y;
            Kt[(d4*4+2) * TP + r] = kv.z;
            Kt[(d4*4+3) * TP + r] = kv.w;
            float4 vv = *(const float4*)(Vg + (size_t)r * D_MODEL + d4 * 4);
            *(float4*)&Vs[r * VP + d4 * 4] = vv;
        }
        __syncthreads();

        // S = Q K^T (8x8 per thread, rank-1 updates over d)
        float S[8][8];
#pragma unroll
        for (int i = 0; i < 8; i++)
#pragma unroll
            for (int j = 0; j < 8; j++) S[i][j] = 0.f;

#pragma unroll 8
        for (int d = 0; d < D_HEAD; d++) {
            float a[8], bb[8];
            *(float4*)&a[0]  = *(const float4*)&Qt[d * TP + ty * 8];
            *(float4*)&a[4]  = *(const float4*)&Qt[d * TP + ty * 8 + 4];
            *(float4*)&bb[0] = *(const float4*)&Kt[d * TP + tx * 8];
            *(float4*)&bb[4] = *(const float4*)&Kt[d * TP + tx * 8 + 4];
#pragma unroll
            for (int i = 0; i < 8; i++)
#pragma unroll
                for (int j = 0; j < 8; j++)
                    S[i][j] += a[i] * bb[j];
        }

        const bool diag = (t == ntiles - 1);

        // Online softmax per owned row; stats reduced across the 16 tx lanes.
#pragma unroll
        for (int i = 0; i < 8; i++) {
            int qi = ty * 8 + i;      // local q row
            float rmax = -1e30f;
#pragma unroll
            for (int j = 0; j < 8; j++) {
                float s = S[i][j];
                if (diag && (tx * 8 + j > qi)) s = -1e30f;   // j0 == q0 on diagonal
                S[i][j] = s;
                rmax = fmaxf(rmax, s);
            }
#pragma unroll
            for (int off = 8; off >= 1; off >>= 1)
                rmax = fmaxf(rmax, __shfl_xor_sync(0xffffffffu, rmax, off, 16));

            float mnew = fmaxf(m_i[i], rmax);
            float corr = __expf(m_i[i] - mnew);
            float rsum = 0.f;
#pragma unroll
            for (int j = 0; j < 8; j++) {
                float p = __expf(S[i][j] - mnew);
                rsum += p;
                Ps[(size_t)(ty * 8 + i) * PSP + tx * 8 + j] = p;
            }
#pragma unroll
            for (int off = 8; off >= 1; off >>= 1)
                rsum += __shfl_xor_sync(0xffffffffu, rsum, off, 16);

            l_i[i] = l_i[i] * corr + rsum;
            m_i[i] = mnew;
            o[i][0] *= corr; o[i][1] *= corr; o[i][2] *= corr; o[i][3] *= corr;
        }
        __syncthreads();

        // O += P @ V   (each thread: rows ty*8..+7, cols tx*4..+3)
#pragma unroll 4
        for (int j = 0; j < BKV; j++) {
            float4 v4 = *(const float4*)&Vs[j * VP + tx * 4];
#pragma unroll
            for (int i = 0; i < 8; i++) {
                float p = Ps[(size_t)(ty * 8 + i) * PSP + j];
                o[i][0] += p * v4.x;
                o[i][1] += p * v4.y;
                o[i][2] += p * v4.z;
                o[i][3] += p * v4.w;
            }
        }
        __syncthreads();
    }

    // Normalize and store [B,L,H,dh] -> row-major [M, D]
#pragma unroll
    for (int i = 0; i < 8; i++) {
        float inv = 1.0f / l_i[i];
        float4 r;
        r.x = o[i][0] * inv; r.y = o[i][1] * inv;
        r.z = o[i][2] * inv; r.w = o[i][3] * inv;
        size_t row = (size_t)(b * SEQ + q0 + ty * 8 + i);
        *(float4*)(g_ao + row * D_MODEL + h * D_HEAD + tx * 4) = r;
    }
}

// ---------------------------------------------------------------------------
extern "C" void kernel_launch(void* const* d_in, const int* in_sizes, int n_in,
                              void* d_out, int out_size)
{
    const float* x  = (const float*)d_in[0];
    const float* Wq = (const float*)d_in[1];
    const float* Wk = (const float*)d_in[2];
    const float* Wv = (const float*)d_in[3];
    const float* Wo = (const float*)d_in[4];
    float* out = (float*)d_out;

    void *pq, *pk, *pv, *pa;
    cudaGetSymbolAddress(&pq, g_q);
    cudaGetSymbolAddress(&pk, g_k);
    cudaGetSymbolAddress(&pv, g_v);
    cudaGetSymbolAddress(&pa, g_ao);

    cudaFuncSetAttribute(flash_attn_causal,
                         cudaFuncAttributeMaxDynamicSharedMemorySize, SMEM_BYTES);

    dim3 ggrid(D_MODEL / BN, M_ROWS / BM);   // (8, 64)
    gemm_nt<<<ggrid, 256>>>(x, Wq, (float*)pq, M_ROWS, D_MODEL, D_MODEL);
    gemm_nt<<<ggrid, 256>>>(x, Wk, (float*)pk, M_ROWS, D_MODEL, D_MODEL);
    gemm_nt<<<ggrid, 256>>>(x, Wv, (float*)pv, M_ROWS, D_MODEL, D_MODEL);

    dim3 fgrid(SEQ / BQ, N_HEADS, B_SZ);     // (16, 16, 4)
    flash_attn_causal<<<fgrid, 256, SMEM_BYTES>>>();

    gemm_nt<<<ggrid, 256>>>((const float*)pa, Wo, out, M_ROWS, D_MODEL, D_MODEL);
}

// round 3
// speedup vs baseline: 1.4992x; 1.4992x over previous
#include <cuda_runtime.h>
#include <cuda_bf16.h>
#include <cstdint>
#include <math.h>

#define D_MODEL 1024
#define N_HEADS 16
#define D_HEAD  64
#define B_SZ    4
#define SEQ     2048
#define M_ROWS  (B_SZ * SEQ)   // 8192
#define K3      (3 * D_MODEL)  // 3072

// ---------------- scratch (__device__ globals; no allocation allowed) -------
__device__ float g_q [M_ROWS * D_MODEL];
__device__ float g_k [M_ROWS * D_MODEL];
__device__ float g_v [M_ROWS * D_MODEL];
__device__ float g_ao[M_ROWS * D_MODEL];

// bf16x3 concatenated operands: A' = [hi | lo | hi], B' = [hi | hi | lo]
__device__ __nv_bfloat16 g_x2 [M_ROWS * K3];          // 48 MB
__device__ __nv_bfloat16 g_ao2[M_ROWS * K3];          // 48 MB
__device__ __nv_bfloat16 g_w2 [4 * D_MODEL * K3];     // 24 MB

// ---------------- fp32 -> 3-slot bf16 split ---------------------------------
// dst row pitch K3. hi written at [c] and [c+hi2]; lo at [c+lo].
__global__ void split3(const float* __restrict__ src, __nv_bfloat16* __restrict__ dst,
                       int n4, int hi2, int lo)
{
    int i = blockIdx.x * 256 + threadIdx.x;
    if (i >= n4) return;
    int r = i >> 8;              // 256 float4 per 1024-col row
    int c = (i & 255) * 4;
    float4 v = ((const float4*)src)[i];
    __nv_bfloat16 h0 = __float2bfloat16(v.x);
    __nv_bfloat16 h1 = __float2bfloat16(v.y);
    __nv_bfloat16 h2 = __float2bfloat16(v.z);
    __nv_bfloat16 h3 = __float2bfloat16(v.w);
    ushort4 H = make_ushort4(__bfloat16_as_ushort(h0), __bfloat16_as_ushort(h1),
                             __bfloat16_as_ushort(h2), __bfloat16_as_ushort(h3));
    ushort4 L = make_ushort4(
        __bfloat16_as_ushort(__float2bfloat16(v.x - __bfloat162float(h0))),
        __bfloat16_as_ushort(__float2bfloat16(v.y - __bfloat162float(h1))),
        __bfloat16_as_ushort(__float2bfloat16(v.z - __bfloat162float(h2))),
        __bfloat16_as_ushort(__float2bfloat16(v.w - __bfloat162float(h3))));
    size_t base = (size_t)r * K3 + c;
    *(ushort4*)(dst + base)       = H;
    *(ushort4*)(dst + base + hi2) = H;
    *(ushort4*)(dst + base + lo)  = L;
}

// ---------------- bf16 NT GEMM via mma.sync (base ISA, HMMA) ---------------
// C[m,n] = sum_k A[m,k] * B[n,k], A:[M,K3], B:[N,K3] bf16; C fp32 [M,1024].
#define BM 128
#define BN 128
#define BKT 32
#define STAGES 4
#define STAGE_BYTES 16384          // A 8KB + B 8KB
#define G_SMEM (STAGES * STAGE_BYTES)
#define NKT (K3 / BKT)             // 96

__device__ __forceinline__ uint32_t smem_u32(const void* p) {
    uint32_t a;
    asm("{ .reg .u64 t; cvta.to.shared.u64 t, %1; cvt.u32.u64 %0, t; }" : "=r"(a) : "l"(p));
    return a;
}
__device__ __forceinline__ void cp_async16(uint32_t s, const void* g) {
    asm volatile("cp.async.cg.shared.global [%0], [%1], 16;" :: "r"(s), "l"(g));
}
#define CP_COMMIT() asm volatile("cp.async.commit_group;" ::: "memory")
#define CP_WAIT2()  asm volatile("cp.async.wait_group 2;" ::: "memory")

__device__ __forceinline__ void ldsm4(uint32_t& r0, uint32_t& r1, uint32_t& r2, uint32_t& r3,
                                      uint32_t addr) {
    asm volatile("ldmatrix.sync.aligned.m8n8.x4.shared.b16 {%0,%1,%2,%3}, [%4];"
                 : "=r"(r0), "=r"(r1), "=r"(r2), "=r"(r3) : "r"(addr));
}
__device__ __forceinline__ void mma16816(float* c, uint32_t a0, uint32_t a1,
                                         uint32_t a2, uint32_t a3,
                                         uint32_t b0, uint32_t b1) {
    asm volatile("mma.sync.aligned.m16n8k16.row.col.f32.bf16.bf16.f32 "
                 "{%0,%1,%2,%3}, {%4,%5,%6,%7}, {%8,%9}, {%0,%1,%2,%3};"
                 : "+f"(c[0]), "+f"(c[1]), "+f"(c[2]), "+f"(c[3])
                 : "r"(a0), "r"(a1), "r"(a2), "r"(a3), "r"(b0), "r"(b1));
}

// swizzled smem byte offset for 16B chunk (row, chunk c in 0..3), 64B rows
__device__ __forceinline__ uint32_t swz(int row, int c) {
    return (uint32_t)(row * 64 + ((c ^ ((row >> 1) & 3)) << 4));
}

__global__ __launch_bounds__(256, 1)
void gemm_bf16(const __nv_bfloat16* __restrict__ A, const __nv_bfloat16* __restrict__ B,
               float* __restrict__ C)
{
    extern __shared__ __align__(128) char sm[];
    const uint32_t sbase = smem_u32(sm);
    const int tid  = threadIdx.x;
    const int lane = tid & 31;
    const int wid  = tid >> 5;
    const int wm   = wid & 3;          // 4 warps along M: 32 rows each
    const int wn   = wid >> 2;         // 2 warps along N: 64 cols each
    const int m0 = blockIdx.y * BM;
    const int n0 = blockIdx.x * BN;

    // per-thread load slots: idx = tid + 256*i -> (row = idx>>2, chunk = idx&3)
    const int lr0 = tid >> 2, lc0 = tid & 3;
    const int lr1 = (tid + 256) >> 2, lc1 = (tid + 256) & 3;

    const __nv_bfloat16* Ag = A + (size_t)(m0 + lr0) * K3 + lc0 * 8;
    const __nv_bfloat16* Ag1 = A + (size_t)(m0 + lr1) * K3 + lc1 * 8;
    const __nv_bfloat16* Bg = B + (size_t)(n0 + lr0) * K3 + lc0 * 8;
    const __nv_bfloat16* Bg1 = B + (size_t)(n0 + lr1) * K3 + lc1 * 8;
    const uint32_t sA0 = swz(lr0, lc0), sA1 = swz(lr1, lc1);

    float acc[2][8][4];
#pragma unroll
    for (int i = 0; i < 2; i++)
#pragma unroll
        for (int j = 0; j < 8; j++)
#pragma unroll
            for (int q = 0; q < 4; q++) acc[i][j][q] = 0.f;

    // prefetch stages 0..2
#pragma unroll
    for (int s = 0; s < STAGES - 1; s++) {
        uint32_t st = sbase + s * STAGE_BYTES;
        cp_async16(st + sA0,        Ag  + s * BKT);
        cp_async16(st + sA1,        Ag1 + s * BKT);
        cp_async16(st + 8192 + sA0, Bg  + s * BKT);
        cp_async16(st + 8192 + sA1, Bg1 + s * BKT);
        CP_COMMIT();
    }

    // ldmatrix lane address components (row offsets within tile)
    const int aRow = wm * 32 + (lane & 15);          // + i*16
    const int aCsel = lane >> 4;                     // 0/1 -> k chunk +0/+1
    const int bRow = wn * 64 + (lane & 7) + ((lane >> 4) << 3);  // + j*16
    const int bCsel = (lane >> 3) & 1;

    for (int kt = 0; kt < NKT; kt++) {
        CP_WAIT2();
        __syncthreads();

        // issue next stage loads (into stage computed 1 iter ago; barrier makes it safe)
        if (kt + STAGES - 1 < NKT) {
            int s = (kt + STAGES - 1) % STAGES;
            int ko = (kt + STAGES - 1) * BKT;
            uint32_t st = sbase + s * STAGE_BYTES;
            cp_async16(st + sA0,        Ag  + ko);
            cp_async16(st + sA1,        Ag1 + ko);
            cp_async16(st + 8192 + sA0, Bg  + ko);
            cp_async16(st + 8192 + sA1, Bg1 + ko);
        }
        CP_COMMIT();

        const uint32_t stA = sbase + (kt % STAGES) * STAGE_BYTES;
        const uint32_t stB = stA + 8192;

#pragma unroll
        for (int k16 = 0; k16 < 2; k16++) {
            const int kc = k16 * 2;       // base 16B chunk of this k16
            uint32_t af[2][4];
#pragma unroll
            for (int i = 0; i < 2; i++) {
                int r = aRow + i * 16;
                ldsm4(af[i][0], af[i][1], af[i][2], af[i][3],
                      stA + swz(r, kc + aCsel));
            }
            uint32_t bf[4][4];
#pragma unroll
            for (int j = 0; j < 4; j++) {
                int r = bRow + j * 16;
                ldsm4(bf[j][0], bf[j][1], bf[j][2], bf[j][3],
                      stB + swz(r, kc + bCsel));
            }
#pragma unroll
            for (int i = 0; i < 2; i++)
#pragma unroll
                for (int j = 0; j < 4; j++) {
                    mma16816(acc[i][2*j+0], af[i][0], af[i][1], af[i][2], af[i][3],
                             bf[j][0], bf[j][1]);
                    mma16816(acc[i][2*j+1], af[i][0], af[i][1], af[i][2], af[i][3],
                             bf[j][2], bf[j][3]);
                }
        }
    }

    // epilogue
    const int gid = lane >> 2, q = lane & 3;
#pragma unroll
    for (int i = 0; i < 2; i++) {
        int r0 = m0 + wm * 32 + i * 16 + gid;
#pragma unroll
        for (int j = 0; j < 8; j++) {
            int col = n0 + wn * 64 + j * 8 + q * 2;
            *(float2*)(C + (size_t)r0 * D_MODEL + col) =
                make_float2(acc[i][j][0], acc[i][j][1]);
            *(float2*)(C + (size_t)(r0 + 8) * D_MODEL + col) =
                make_float2(acc[i][j][2], acc[i][j][3]);
        }
    }
}

// ---------------------------------------------------------------------------
// Flash attention (fp32, causal) — unchanged (proven in round 1).
// ---------------------------------------------------------------------------
#define BQ  128
#define BKV 128
#define TP  (BQ + 4)
#define VP  (D_HEAD + 4)
#define PSP (BKV + 4)

#define SM_QT   0
#define SM_KT   (D_HEAD * TP)
#define SM_VS   (SM_KT + D_HEAD * TP)
#define SM_PS   (SM_VS + BKV * VP)
#define SM_FLOATS (SM_PS + BQ * PSP)
#define SMEM_BYTES (SM_FLOATS * 4)

__global__ __launch_bounds__(256, 1)
void flash_attn_causal()
{
    extern __shared__ __align__(16) float smf[];
    float* Qt = smf + SM_QT;
    float* Kt = smf + SM_KT;
    float* Vs = smf + SM_VS;
    float* Ps = smf + SM_PS;

    const int tid = threadIdx.x;
    const int tx = tid & 15;
    const int ty = tid >> 4;
    const int qt = blockIdx.x;
    const int h  = blockIdx.y;
    const int b  = blockIdx.z;
    const int q0 = qt * BQ;
    const float scale = 0.125f;

    const float* Qg = g_q + ((size_t)(b * SEQ + q0)) * D_MODEL + h * D_HEAD;
#pragma unroll
    for (int it = 0; it < 8; it++) {
        int idx = tid + it * 256;
        int r  = idx >> 4;
        int d4 = idx & 15;
        float4 v = *(const float4*)(Qg + (size_t)r * D_MODEL + d4 * 4);
        Qt[(d4*4+0) * TP + r] = v.x * scale;
        Qt[(d4*4+1) * TP + r] = v.y * scale;
        Qt[(d4*4+2) * TP + r] = v.z * scale;
        Qt[(d4*4+3) * TP + r] = v.w * scale;
    }

    float m_i[8], l_i[8], o[8][4];
#pragma unroll
    for (int i = 0; i < 8; i++) {
        m_i[i] = -1e30f; l_i[i] = 0.f;
        o[i][0] = o[i][1] = o[i][2] = o[i][3] = 0.f;
    }

    const int ntiles = qt + 1;
    for (int t = 0; t < ntiles; t++) {
        const int j0 = t * BKV;
        const float* Kg = g_k + ((size_t)(b * SEQ + j0)) * D_MODEL + h * D_HEAD;
        const float* Vg = g_v + ((size_t)(b * SEQ + j0)) * D_MODEL + h * D_HEAD;
#pragma unroll
        for (int it = 0; it < 8; it++) {
            int idx = tid + it * 256;
            int r  = idx >> 4;
            int d4 = idx & 15;
            float4 kv = *(const float4*)(Kg + (size_t)r * D_MODEL + d4 * 4);
            Kt[(d4*4+0) * TP + r] = kv.x;
            Kt[(d4*4+1) * TP + r] = kv.y;
            Kt[(d4*4+2) * TP + r] = kv.z;
            Kt[(d4*4+3) * TP + r] = kv.w;
            float4 vv = *(const float4*)(Vg + (size_t)r * D_MODEL + d4 * 4);
            *(float4*)&Vs[r * VP + d4 * 4] = vv;
        }
        __syncthreads();

        float S[8][8];
#pragma unroll
        for (int i = 0; i < 8; i++)
#pragma unroll
            for (int j = 0; j < 8; j++) S[i][j] = 0.f;

#pragma unroll 8
        for (int d = 0; d < D_HEAD; d++) {
            float a[8], bb[8];
            *(float4*)&a[0]  = *(const float4*)&Qt[d * TP + ty * 8];
            *(float4*)&a[4]  = *(const float4*)&Qt[d * TP + ty * 8 + 4];
            *(float4*)&bb[0] = *(const float4*)&Kt[d * TP + tx * 8];
            *(float4*)&bb[4] = *(const float4*)&Kt[d * TP + tx * 8 + 4];
#pragma unroll
            for (int i = 0; i < 8; i++)
#pragma unroll
                for (int j = 0; j < 8; j++)
                    S[i][j] += a[i] * bb[j];
        }

        const bool diag = (t == ntiles - 1);
#pragma unroll
        for (int i = 0; i < 8; i++) {
            int qi = ty * 8 + i;
            float rmax = -1e30f;
#pragma unroll
            for (int j = 0; j < 8; j++) {
                float s = S[i][j];
                if (diag && (tx * 8 + j > qi)) s = -1e30f;
                S[i][j] = s;
                rmax = fmaxf(rmax, s);
            }
#pragma unroll
            for (int off = 8; off >= 1; off >>= 1)
                rmax = fmaxf(rmax, __shfl_xor_sync(0xffffffffu, rmax, off, 16));

            float mnew = fmaxf(m_i[i], rmax);
            float corr = __expf(m_i[i] - mnew);
            float rsum = 0.f;
#pragma unroll
            for (int j = 0; j < 8; j++) {
                float p = __expf(S[i][j] - mnew);
                rsum += p;
                Ps[(size_t)(ty * 8 + i) * PSP + tx * 8 + j] = p;
            }
#pragma unroll
            for (int off = 8; off >= 1; off >>= 1)
                rsum += __shfl_xor_sync(0xffffffffu, rsum, off, 16);

            l_i[i] = l_i[i] * corr + rsum;
            m_i[i] = mnew;
            o[i][0] *= corr; o[i][1] *= corr; o[i][2] *= corr; o[i][3] *= corr;
        }
        __syncthreads();

#pragma unroll 4
        for (int j = 0; j < BKV; j++) {
            float4 v4 = *(const float4*)&Vs[j * VP + tx * 4];
#pragma unroll
            for (int i = 0; i < 8; i++) {
                float p = Ps[(size_t)(ty * 8 + i) * PSP + j];
                o[i][0] += p * v4.x;
                o[i][1] += p * v4.y;
                o[i][2] += p * v4.z;
                o[i][3] += p * v4.w;
            }
        }
        __syncthreads();
    }

#pragma unroll
    for (int i = 0; i < 8; i++) {
        float inv = 1.0f / l_i[i];
        float4 r;
        r.x = o[i][0] * inv; r.y = o[i][1] * inv;
        r.z = o[i][2] * inv; r.w = o[i][3] * inv;
        size_t row = (size_t)(b * SEQ + q0 + ty * 8 + i);
        *(float4*)(g_ao + row * D_MODEL + h * D_HEAD + tx * 4) = r;
    }
}

// ---------------------------------------------------------------------------
extern "C" void kernel_launch(void* const* d_in, const int* in_sizes, int n_in,
                              void* d_out, int out_size)
{
    const float* x  = (const float*)d_in[0];
    const float* Wq = (const float*)d_in[1];
    const float* Wk = (const float*)d_in[2];
    const float* Wv = (const float*)d_in[3];
    const float* Wo = (const float*)d_in[4];
    float* out = (float*)d_out;

    void *pq, *pk, *pv, *pa, *px2, *pa2, *pw2;
    cudaGetSymbolAddress(&pq,  g_q);
    cudaGetSymbolAddress(&pk,  g_k);
    cudaGetSymbolAddress(&pv,  g_v);
    cudaGetSymbolAddress(&pa,  g_ao);
    cudaGetSymbolAddress(&px2, g_x2);
    cudaGetSymbolAddress(&pa2, g_ao2);
    cudaGetSymbolAddress(&pw2, g_w2);

    __nv_bfloat16* x2  = (__nv_bfloat16*)px2;
    __nv_bfloat16* ao2 = (__nv_bfloat16*)pa2;
    __nv_bfloat16* w2  = (__nv_bfloat16*)pw2;

    cudaFuncSetAttribute(gemm_bf16,
                         cudaFuncAttributeMaxDynamicSharedMemorySize, G_SMEM);
    cudaFuncSetAttribute(flash_attn_causal,
                         cudaFuncAttributeMaxDynamicSharedMemorySize, SMEM_BYTES);

    const int n4x = M_ROWS * D_MODEL / 4;
    const int n4w = D_MODEL * D_MODEL / 4;
    const size_t WSZ = (size_t)D_MODEL * K3;

    // activations: A-type split (hi | lo | hi) ; weights: B-type (hi | hi | lo)
    split3<<<(n4x + 255) / 256, 256>>>(x, x2, n4x, 2048, 1024);
    split3<<<(n4w + 255) / 256, 256>>>(Wq, w2 + 0 * WSZ, n4w, 1024, 2048);
    split3<<<(n4w + 255) / 256, 256>>>(Wk, w2 + 1 * WSZ, n4w, 1024, 2048);
    split3<<<(n4w + 255) / 256, 256>>>(Wv, w2 + 2 * WSZ, n4w, 1024, 2048);
    split3<<<(n4w + 255) / 256, 256>>>(Wo, w2 + 3 * WSZ, n4w, 1024, 2048);

    dim3 ggrid(D_MODEL / BN, M_ROWS / BM);   // (8, 64)
    gemm_bf16<<<ggrid, 256, G_SMEM>>>(x2, w2 + 0 * WSZ, (float*)pq);
    gemm_bf16<<<ggrid, 256, G_SMEM>>>(x2, w2 + 1 * WSZ, (float*)pk);
    gemm_bf16<<<ggrid, 256, G_SMEM>>>(x2, w2 + 2 * WSZ, (float*)pv);

    dim3 fgrid(SEQ / BQ, N_HEADS, B_SZ);
    flash_attn_causal<<<fgrid, 256, SMEM_BYTES>>>();

    split3<<<(n4x + 255) / 256, 256>>>((const float*)pa, ao2, n4x, 2048, 1024);
    gemm_bf16<<<ggrid, 256, G_SMEM>>>(ao2, w2 + 3 * WSZ, out);
}

// round 4
// speedup vs baseline: 1.6437x; 1.0964x over previous
#include <cuda_runtime.h>
#include <cuda_bf16.h>
#include <cstdint>
#include <math.h>

#define D_MODEL 1024
#define N_HEADS 16
#define D_HEAD  64
#define B_SZ    4
#define SEQ     2048
#define M_ROWS  (B_SZ * SEQ)   // 8192
#define K3      (3 * D_MODEL)  // 3072

// ---------------- scratch (__device__ globals) ------------------------------
__device__ float g_qkv[M_ROWS * K3];                  // fused q|k|v fp32, 96 MB
__device__ float g_ao [M_ROWS * D_MODEL];

__device__ __nv_bfloat16 g_x2 [M_ROWS * K3];          // A' = [hi | lo | hi]
__device__ __nv_bfloat16 g_ao2[M_ROWS * K3];
__device__ __nv_bfloat16 g_w2 [4 * D_MODEL * K3];     // B' = [hi | hi | lo] x4 weights

// ---------------- fp32 -> 3-slot bf16 split ---------------------------------
__global__ void split3(const float* __restrict__ src, __nv_bfloat16* __restrict__ dst,
                       int n4, int hi2, int lo)
{
    int i = blockIdx.x * 256 + threadIdx.x;
    if (i >= n4) return;
    int r = i >> 8;
    int c = (i & 255) * 4;
    float4 v = ((const float4*)src)[i];
    __nv_bfloat16 h0 = __float2bfloat16(v.x);
    __nv_bfloat16 h1 = __float2bfloat16(v.y);
    __nv_bfloat16 h2 = __float2bfloat16(v.z);
    __nv_bfloat16 h3 = __float2bfloat16(v.w);
    ushort4 H = make_ushort4(__bfloat16_as_ushort(h0), __bfloat16_as_ushort(h1),
                             __bfloat16_as_ushort(h2), __bfloat16_as_ushort(h3));
    ushort4 L = make_ushort4(
        __bfloat16_as_ushort(__float2bfloat16(v.x - __bfloat162float(h0))),
        __bfloat16_as_ushort(__float2bfloat16(v.y - __bfloat162float(h1))),
        __bfloat16_as_ushort(__float2bfloat16(v.z - __bfloat162float(h2))),
        __bfloat16_as_ushort(__float2bfloat16(v.w - __bfloat162float(h3))));
    size_t base = (size_t)r * K3 + c;
    *(ushort4*)(dst + base)       = H;
    *(ushort4*)(dst + base + hi2) = H;
    *(ushort4*)(dst + base + lo)  = L;
}

// ---------------- bf16 NT GEMM via mma.sync (HMMA) --------------------------
#define BM 128
#define BN 128
#define BKT 32
#define STAGES 3
#define STAGE_BYTES 16384
#define G_SMEM (STAGES * STAGE_BYTES)    // 48 KB -> 2 CTAs/SM
#define NKT (K3 / BKT)                   // 96

__device__ __forceinline__ uint32_t smem_u32(const void* p) {
    uint32_t a;
    asm("{ .reg .u64 t; cvta.to.shared.u64 t, %1; cvt.u32.u64 %0, t; }" : "=r"(a) : "l"(p));
    return a;
}
__device__ __forceinline__ void cp_async16(uint32_t s, const void* g) {
    asm volatile("cp.async.cg.shared.global [%0], [%1], 16;" :: "r"(s), "l"(g));
}
#define CP_COMMIT() asm volatile("cp.async.commit_group;" ::: "memory")
#define CP_WAIT1()  asm volatile("cp.async.wait_group 1;" ::: "memory")

__device__ __forceinline__ void ldsm4(uint32_t& r0, uint32_t& r1, uint32_t& r2, uint32_t& r3,
                                      uint32_t addr) {
    asm volatile("ldmatrix.sync.aligned.m8n8.x4.shared.b16 {%0,%1,%2,%3}, [%4];"
                 : "=r"(r0), "=r"(r1), "=r"(r2), "=r"(r3) : "r"(addr));
}
__device__ __forceinline__ void mma16816(float* c, uint32_t a0, uint32_t a1,
                                         uint32_t a2, uint32_t a3,
                                         uint32_t b0, uint32_t b1) {
    asm volatile("mma.sync.aligned.m16n8k16.row.col.f32.bf16.bf16.f32 "
                 "{%0,%1,%2,%3}, {%4,%5,%6,%7}, {%8,%9}, {%0,%1,%2,%3};"
                 : "+f"(c[0]), "+f"(c[1]), "+f"(c[2]), "+f"(c[3])
                 : "r"(a0), "r"(a1), "r"(a2), "r"(a3), "r"(b0), "r"(b1));
}
__device__ __forceinline__ uint32_t swz(int row, int c) {
    return (uint32_t)(row * 64 + ((c ^ ((row >> 1) & 3)) << 4));
}

__global__ __launch_bounds__(256, 2)
void gemm_bf16(const __nv_bfloat16* __restrict__ A, const __nv_bfloat16* __restrict__ B,
               float* __restrict__ C, int cpitch)
{
    extern __shared__ __align__(128) char sm[];
    const uint32_t sbase = smem_u32(sm);
    const int tid  = threadIdx.x;
    const int lane = tid & 31;
    const int wid  = tid >> 5;
    const int wm   = wid & 3;
    const int wn   = wid >> 2;
    const int m0 = blockIdx.y * BM;
    const int n0 = blockIdx.x * BN;

    const int lr0 = tid >> 2, lc0 = tid & 3;
    const int lr1 = (tid + 256) >> 2, lc1 = (tid + 256) & 3;

    const __nv_bfloat16* Ag  = A + (size_t)(m0 + lr0) * K3 + lc0 * 8;
    const __nv_bfloat16* Ag1 = A + (size_t)(m0 + lr1) * K3 + lc1 * 8;
    const __nv_bfloat16* Bg  = B + (size_t)(n0 + lr0) * K3 + lc0 * 8;
    const __nv_bfloat16* Bg1 = B + (size_t)(n0 + lr1) * K3 + lc1 * 8;
    const uint32_t sA0 = swz(lr0, lc0), sA1 = swz(lr1, lc1);

    float acc[2][8][4];
#pragma unroll
    for (int i = 0; i < 2; i++)
#pragma unroll
        for (int j = 0; j < 8; j++)
#pragma unroll
            for (int q = 0; q < 4; q++) acc[i][j][q] = 0.f;

#pragma unroll
    for (int s = 0; s < STAGES - 1; s++) {
        uint32_t st = sbase + s * STAGE_BYTES;
        cp_async16(st + sA0,        Ag  + s * BKT);
        cp_async16(st + sA1,        Ag1 + s * BKT);
        cp_async16(st + 8192 + sA0, Bg  + s * BKT);
        cp_async16(st + 8192 + sA1, Bg1 + s * BKT);
        CP_COMMIT();
    }

    const int aRow = wm * 32 + (lane & 15);
    const int aCsel = lane >> 4;
    const int bRow = wn * 64 + (lane & 7) + ((lane >> 4) << 3);
    const int bCsel = (lane >> 3) & 1;

    for (int kt = 0; kt < NKT; kt++) {
        CP_WAIT1();
        __syncthreads();

        if (kt + STAGES - 1 < NKT) {
            int s = (kt + STAGES - 1) % STAGES;
            int ko = (kt + STAGES - 1) * BKT;
            uint32_t st = sbase + s * STAGE_BYTES;
            cp_async16(st + sA0,        Ag  + ko);
            cp_async16(st + sA1,        Ag1 + ko);
            cp_async16(st + 8192 + sA0, Bg  + ko);
            cp_async16(st + 8192 + sA1, Bg1 + ko);
        }
        CP_COMMIT();

        const uint32_t stA = sbase + (kt % STAGES) * STAGE_BYTES;
        const uint32_t stB = stA + 8192;

#pragma unroll
        for (int k16 = 0; k16 < 2; k16++) {
            const int kc = k16 * 2;
            uint32_t af[2][4];
#pragma unroll
            for (int i = 0; i < 2; i++) {
                int r = aRow + i * 16;
                ldsm4(af[i][0], af[i][1], af[i][2], af[i][3],
                      stA + swz(r, kc + aCsel));
            }
            uint32_t bf[4][4];
#pragma unroll
            for (int j = 0; j < 4; j++) {
                int r = bRow + j * 16;
                ldsm4(bf[j][0], bf[j][1], bf[j][2], bf[j][3],
                      stB + swz(r, kc + bCsel));
            }
#pragma unroll
            for (int i = 0; i < 2; i++)
#pragma unroll
                for (int j = 0; j < 4; j++) {
                    mma16816(acc[i][2*j+0], af[i][0], af[i][1], af[i][2], af[i][3],
                             bf[j][0], bf[j][1]);
                    mma16816(acc[i][2*j+1], af[i][0], af[i][1], af[i][2], af[i][3],
                             bf[j][2], bf[j][3]);
                }
        }
    }

    const int gid = lane >> 2, q = lane & 3;
#pragma unroll
    for (int i = 0; i < 2; i++) {
        int r0 = m0 + wm * 32 + i * 16 + gid;
#pragma unroll
        for (int j = 0; j < 8; j++) {
            int col = n0 + wn * 64 + j * 8 + q * 2;
            *(float2*)(C + (size_t)r0 * cpitch + col) =
                make_float2(acc[i][j][0], acc[i][j][1]);
            *(float2*)(C + (size_t)(r0 + 8) * cpitch + col) =
                make_float2(acc[i][j][2], acc[i][j][3]);
        }
    }
}

// ---------------------------------------------------------------------------
// Flash attention (fp32, causal). Reads fused qkv buffer (row pitch K3).
// ---------------------------------------------------------------------------
#define BQ  128
#define BKV 128
#define TP  (BQ + 4)
#define VP  (D_HEAD + 4)
#define PSP (BKV + 4)

#define SM_QT   0
#define SM_KT   (D_HEAD * TP)
#define SM_VS   (SM_KT + D_HEAD * TP)
#define SM_PS   (SM_VS + BKV * VP)
#define SM_FLOATS (SM_PS + BQ * PSP)
#define SMEM_BYTES (SM_FLOATS * 4)

__global__ __launch_bounds__(256, 1)
void flash_attn_causal()
{
    extern __shared__ __align__(16) float smf[];
    float* Qt = smf + SM_QT;
    float* Kt = smf + SM_KT;
    float* Vs = smf + SM_VS;
    float* Ps = smf + SM_PS;

    const int tid = threadIdx.x;
    const int tx = tid & 15;
    const int ty = tid >> 4;
    const int qt = blockIdx.x;
    const int h  = blockIdx.y;
    const int b  = blockIdx.z;
    const int q0 = qt * BQ;
    const float scale = 0.125f;

    const float* Qg = g_qkv + ((size_t)(b * SEQ + q0)) * K3 + h * D_HEAD;
#pragma unroll
    for (int it = 0; it < 8; it++) {
        int idx = tid + it * 256;
        int r  = idx >> 4;
        int d4 = idx & 15;
        float4 v = *(const float4*)(Qg + (size_t)r * K3 + d4 * 4);
        Qt[(d4*4+0) * TP + r] = v.x * scale;
        Qt[(d4*4+1) * TP + r] = v.y * scale;
        Qt[(d4*4+2) * TP + r] = v.z * scale;
        Qt[(d4*4+3) * TP + r] = v.w * scale;
    }

    float m_i[8], l_i[8], o[8][4];
#pragma unroll
    for (int i = 0; i < 8; i++) {
        m_i[i] = -1e30f; l_i[i] = 0.f;
        o[i][0] = o[i][1] = o[i][2] = o[i][3] = 0.f;
    }

    const int ntiles = qt + 1;
    for (int t = 0; t < ntiles; t++) {
        const int j0 = t * BKV;
        const float* Kg = g_qkv + ((size_t)(b * SEQ + j0)) * K3 + D_MODEL + h * D_HEAD;
        const float* Vg = g_qkv + ((size_t)(b * SEQ + j0)) * K3 + 2 * D_MODEL + h * D_HEAD;
#pragma unroll
        for (int it = 0; it < 8; it++) {
            int idx = tid + it * 256;
            int r  = idx >> 4;
            int d4 = idx & 15;
            float4 kv = *(const float4*)(Kg + (size_t)r * K3 + d4 * 4);
            Kt[(d4*4+0) * TP + r] = kv.x;
            Kt[(d4*4+1) * TP + r] = kv.y;
            Kt[(d4*4+2) * TP + r] = kv.z;
            Kt[(d4*4+3) * TP + r] = kv.w;
            float4 vv = *(const float4*)(Vg + (size_t)r * K3 + d4 * 4);
            *(float4*)&Vs[r * VP + d4 * 4] = vv;
        }
        __syncthreads();

        float S[8][8];
#pragma unroll
        for (int i = 0; i < 8; i++)
#pragma unroll
            for (int j = 0; j < 8; j++) S[i][j] = 0.f;

#pragma unroll 8
        for (int d = 0; d < D_HEAD; d++) {
            float a[8], bb[8];
            *(float4*)&a[0]  = *(const float4*)&Qt[d * TP + ty * 8];
            *(float4*)&a[4]  = *(const float4*)&Qt[d * TP + ty * 8 + 4];
            *(float4*)&bb[0] = *(const float4*)&Kt[d * TP + tx * 8];
            *(float4*)&bb[4] = *(const float4*)&Kt[d * TP + tx * 8 + 4];
#pragma unroll
            for (int i = 0; i < 8; i++)
#pragma unroll
                for (int j = 0; j < 8; j++)
                    S[i][j] += a[i] * bb[j];
        }

        const bool diag = (t == ntiles - 1);
#pragma unroll
        for (int i = 0; i < 8; i++) {
            int qi = ty * 8 + i;
            float rmax = -1e30f;
#pragma unroll
            for (int j = 0; j < 8; j++) {
                float s = S[i][j];
                if (diag && (tx * 8 + j > qi)) s = -1e30f;
                S[i][j] = s;
                rmax = fmaxf(rmax, s);
            }
#pragma unroll
            for (int off = 8; off >= 1; off >>= 1)
                rmax = fmaxf(rmax, __shfl_xor_sync(0xffffffffu, rmax, off, 16));

            float mnew = fmaxf(m_i[i], rmax);
            float corr = __expf(m_i[i] - mnew);
            float rsum = 0.f;
#pragma unroll
            for (int j = 0; j < 8; j++) {
                float p = __expf(S[i][j] - mnew);
                rsum += p;
                Ps[(size_t)(ty * 8 + i) * PSP + tx * 8 + j] = p;
            }
#pragma unroll
            for (int off = 8; off >= 1; off >>= 1)
                rsum += __shfl_xor_sync(0xffffffffu, rsum, off, 16);

            l_i[i] = l_i[i] * corr + rsum;
            m_i[i] = mnew;
            o[i][0] *= corr; o[i][1] *= corr; o[i][2] *= corr; o[i][3] *= corr;
        }
        __syncthreads();

#pragma unroll 4
        for (int j = 0; j < BKV; j++) {
            float4 v4 = *(const float4*)&Vs[j * VP + tx * 4];
#pragma unroll
            for (int i = 0; i < 8; i++) {
                float p = Ps[(size_t)(ty * 8 + i) * PSP + j];
                o[i][0] += p * v4.x;
                o[i][1] += p * v4.y;
                o[i][2] += p * v4.z;
                o[i][3] += p * v4.w;
            }
        }
        __syncthreads();
    }

#pragma unroll
    for (int i = 0; i < 8; i++) {
        float inv = 1.0f / l_i[i];
        float4 r;
        r.x = o[i][0] * inv; r.y = o[i][1] * inv;
        r.z = o[i][2] * inv; r.w = o[i][3] * inv;
        size_t row = (size_t)(b * SEQ + q0 + ty * 8 + i);
        *(float4*)(g_ao + row * D_MODEL + h * D_HEAD + tx * 4) = r;
    }
}

// ---------------------------------------------------------------------------
extern "C" void kernel_launch(void* const* d_in, const int* in_sizes, int n_in,
                              void* d_out, int out_size)
{
    const float* x  = (const float*)d_in[0];
    const float* Wq = (const float*)d_in[1];
    const float* Wk = (const float*)d_in[2];
    const float* Wv = (const float*)d_in[3];
    const float* Wo = (const float*)d_in[4];
    float* out = (float*)d_out;

    void *pqkv, *pa, *px2, *pa2, *pw2;
    cudaGetSymbolAddress(&pqkv, g_qkv);
    cudaGetSymbolAddress(&pa,   g_ao);
    cudaGetSymbolAddress(&px2,  g_x2);
    cudaGetSymbolAddress(&pa2,  g_ao2);
    cudaGetSymbolAddress(&pw2,  g_w2);

    __nv_bfloat16* x2  = (__nv_bfloat16*)px2;
    __nv_bfloat16* ao2 = (__nv_bfloat16*)pa2;
    __nv_bfloat16* w2  = (__nv_bfloat16*)pw2;

    cudaFuncSetAttribute(gemm_bf16,
                         cudaFuncAttributeMaxDynamicSharedMemorySize, G_SMEM);
    cudaFuncSetAttribute(flash_attn_causal,
                         cudaFuncAttributeMaxDynamicSharedMemorySize, SMEM_BYTES);

    const int n4x = M_ROWS * D_MODEL / 4;
    const int n4w = D_MODEL * D_MODEL / 4;
    const size_t WSZ = (size_t)D_MODEL * K3;

    split3<<<(n4x + 255) / 256, 256>>>(x, x2, n4x, 2048, 1024);
    split3<<<(n4w + 255) / 256, 256>>>(Wq, w2 + 0 * WSZ, n4w, 1024, 2048);
    split3<<<(n4w + 255) / 256, 256>>>(Wk, w2 + 1 * WSZ, n4w, 1024, 2048);
    split3<<<(n4w + 255) / 256, 256>>>(Wv, w2 + 2 * WSZ, n4w, 1024, 2048);
    split3<<<(n4w + 255) / 256, 256>>>(Wo, w2 + 3 * WSZ, n4w, 1024, 2048);

    // Fused QKV: B' = [Wq';Wk';Wv'] is rows 0..3071 of w2 -> one GEMM, N=3072
    dim3 qkvgrid(K3 / BN, M_ROWS / BM);      // (24, 64)
    gemm_bf16<<<qkvgrid, 256, G_SMEM>>>(x2, w2, (float*)pqkv, K3);

    dim3 fgrid(SEQ / BQ, N_HEADS, B_SZ);
    flash_attn_causal<<<fgrid, 256, SMEM_BYTES>>>();

    split3<<<(n4x + 255) / 256, 256>>>((const float*)pa, ao2, n4x, 2048, 1024);
    dim3 ogrid(D_MODEL / BN, M_ROWS / BM);   // (8, 64)
    gemm_bf16<<<ogrid, 256, G_SMEM>>>(ao2, w2 + 3 * WSZ, out, D_MODEL);
}

// round 5
// speedup vs baseline: 2.9174x; 1.7749x over previous
#include <cuda_runtime.h>
#include <cuda_bf16.h>
#include <cuda_fp16.h>
#include <cstdint>
#include <math.h>

#define D_MODEL 1024
#define N_HEADS 16
#define D_HEAD  64
#define B_SZ    4
#define SEQ     2048
#define M_ROWS  (B_SZ * SEQ)   // 8192
#define K3      (3 * D_MODEL)  // 3072

// ---------------- scratch (__device__ globals) ------------------------------
__device__ float g_qkv[M_ROWS * K3];                  // fused q|k|v fp32
__device__ float g_ao [M_ROWS * D_MODEL];

__device__ __nv_bfloat16 g_x2 [M_ROWS * K3];          // A' = [hi | lo | hi]
__device__ __nv_bfloat16 g_ao2[M_ROWS * K3];
__device__ __nv_bfloat16 g_w2 [4 * D_MODEL * K3];     // B' = [hi | hi | lo] x4

// ---------------- fp32 -> 3-slot bf16 split ---------------------------------
__global__ void split3(const float* __restrict__ src, __nv_bfloat16* __restrict__ dst,
                       int n4, int hi2, int lo)
{
    int i = blockIdx.x * 256 + threadIdx.x;
    if (i >= n4) return;
    int r = i >> 8;
    int c = (i & 255) * 4;
    float4 v = ((const float4*)src)[i];
    __nv_bfloat16 h0 = __float2bfloat16(v.x);
    __nv_bfloat16 h1 = __float2bfloat16(v.y);
    __nv_bfloat16 h2 = __float2bfloat16(v.z);
    __nv_bfloat16 h3 = __float2bfloat16(v.w);
    ushort4 H = make_ushort4(__bfloat16_as_ushort(h0), __bfloat16_as_ushort(h1),
                             __bfloat16_as_ushort(h2), __bfloat16_as_ushort(h3));
    ushort4 L = make_ushort4(
        __bfloat16_as_ushort(__float2bfloat16(v.x - __bfloat162float(h0))),
        __bfloat16_as_ushort(__float2bfloat16(v.y - __bfloat162float(h1))),
        __bfloat16_as_ushort(__float2bfloat16(v.z - __bfloat162float(h2))),
        __bfloat16_as_ushort(__float2bfloat16(v.w - __bfloat162float(h3))));
    size_t base = (size_t)r * K3 + c;
    *(ushort4*)(dst + base)       = H;
    *(ushort4*)(dst + base + hi2) = H;
    *(ushort4*)(dst + base + lo)  = L;
}

// ---------------- common helpers --------------------------------------------
__device__ __forceinline__ uint32_t smem_u32(const void* p) {
    uint32_t a;
    asm("{ .reg .u64 t; cvta.to.shared.u64 t, %1; cvt.u32.u64 %0, t; }" : "=r"(a) : "l"(p));
    return a;
}
__device__ __forceinline__ void cp_async16(uint32_t s, const void* g) {
    asm volatile("cp.async.cg.shared.global [%0], [%1], 16;" :: "r"(s), "l"(g));
}
#define CP_COMMIT() asm volatile("cp.async.commit_group;" ::: "memory")
#define CP_WAIT1()  asm volatile("cp.async.wait_group 1;" ::: "memory")

__device__ __forceinline__ void ldsm4(uint32_t& r0, uint32_t& r1, uint32_t& r2, uint32_t& r3,
                                      uint32_t addr) {
    asm volatile("ldmatrix.sync.aligned.m8n8.x4.shared.b16 {%0,%1,%2,%3}, [%4];"
                 : "=r"(r0), "=r"(r1), "=r"(r2), "=r"(r3) : "r"(addr));
}
__device__ __forceinline__ void mma16816(float* c, uint32_t a0, uint32_t a1,
                                         uint32_t a2, uint32_t a3,
                                         uint32_t b0, uint32_t b1) {
    asm volatile("mma.sync.aligned.m16n8k16.row.col.f32.bf16.bf16.f32 "
                 "{%0,%1,%2,%3}, {%4,%5,%6,%7}, {%8,%9}, {%0,%1,%2,%3};"
                 : "+f"(c[0]), "+f"(c[1]), "+f"(c[2]), "+f"(c[3])
                 : "r"(a0), "r"(a1), "r"(a2), "r"(a3), "r"(b0), "r"(b1));
}
__device__ __forceinline__ void mma16816h(float* c, uint32_t a0, uint32_t a1,
                                          uint32_t a2, uint32_t a3,
                                          uint32_t b0, uint32_t b1) {
    asm volatile("mma.sync.aligned.m16n8k16.row.col.f32.f16.f16.f32 "
                 "{%0,%1,%2,%3}, {%4,%5,%6,%7}, {%8,%9}, {%0,%1,%2,%3};"
                 : "+f"(c[0]), "+f"(c[1]), "+f"(c[2]), "+f"(c[3])
                 : "r"(a0), "r"(a1), "r"(a2), "r"(a3), "r"(b0), "r"(b1));
}
__device__ __forceinline__ uint32_t swz(int row, int c) {          // 64B rows
    return (uint32_t)(row * 64 + ((c ^ ((row >> 1) & 3)) << 4));
}
__device__ __forceinline__ uint32_t swz128(int row, int c) {       // 128B rows
    return (uint32_t)(row * 128 + ((c ^ (row & 7)) << 4));
}
__device__ __forceinline__ uint32_t swzV(int row, int c) {         // 256B rows
    return (uint32_t)(row * 256 + ((c ^ (row & 7)) << 4));
}
__device__ __forceinline__ uint32_t pack_h2(float a, float b) {
    __half2 h = __floats2half2_rn(a, b);
    return *(uint32_t*)&h;
}

// ---------------- bf16 NT GEMM via mma.sync (HMMA) --------------------------
#define BM 128
#define BN 128
#define BKT 32
#define STAGES 3
#define STAGE_BYTES 16384
#define G_SMEM (STAGES * STAGE_BYTES)
#define NKT (K3 / BKT)

__global__ __launch_bounds__(256, 2)
void gemm_bf16(const __nv_bfloat16* __restrict__ A, const __nv_bfloat16* __restrict__ B,
               float* __restrict__ C, int cpitch)
{
    extern __shared__ __align__(128) char sm[];
    const uint32_t sbase = smem_u32(sm);
    const int tid  = threadIdx.x;
    const int lane = tid & 31;
    const int wid  = tid >> 5;
    const int wm   = wid & 3;
    const int wn   = wid >> 2;
    const int m0 = blockIdx.y * BM;
    const int n0 = blockIdx.x * BN;

    const int lr0 = tid >> 2, lc0 = tid & 3;
    const int lr1 = (tid + 256) >> 2, lc1 = (tid + 256) & 3;

    const __nv_bfloat16* Ag  = A + (size_t)(m0 + lr0) * K3 + lc0 * 8;
    const __nv_bfloat16* Ag1 = A + (size_t)(m0 + lr1) * K3 + lc1 * 8;
    const __nv_bfloat16* Bg  = B + (size_t)(n0 + lr0) * K3 + lc0 * 8;
    const __nv_bfloat16* Bg1 = B + (size_t)(n0 + lr1) * K3 + lc1 * 8;
    const uint32_t sA0 = swz(lr0, lc0), sA1 = swz(lr1, lc1);

    float acc[2][8][4];
#pragma unroll
    for (int i = 0; i < 2; i++)
#pragma unroll
        for (int j = 0; j < 8; j++)
#pragma unroll
            for (int q = 0; q < 4; q++) acc[i][j][q] = 0.f;

#pragma unroll
    for (int s = 0; s < STAGES - 1; s++) {
        uint32_t st = sbase + s * STAGE_BYTES;
        cp_async16(st + sA0,        Ag  + s * BKT);
        cp_async16(st + sA1,        Ag1 + s * BKT);
        cp_async16(st + 8192 + sA0, Bg  + s * BKT);
        cp_async16(st + 8192 + sA1, Bg1 + s * BKT);
        CP_COMMIT();
    }

    const int aRow = wm * 32 + (lane & 15);
    const int aCsel = lane >> 4;
    const int bRow = wn * 64 + (lane & 7) + ((lane >> 4) << 3);
    const int bCsel = (lane >> 3) & 1;

    for (int kt = 0; kt < NKT; kt++) {
        CP_WAIT1();
        __syncthreads();

        if (kt + STAGES - 1 < NKT) {
            int s = (kt + STAGES - 1) % STAGES;
            int ko = (kt + STAGES - 1) * BKT;
            uint32_t st = sbase + s * STAGE_BYTES;
            cp_async16(st + sA0,        Ag  + ko);
            cp_async16(st + sA1,        Ag1 + ko);
            cp_async16(st + 8192 + sA0, Bg  + ko);
            cp_async16(st + 8192 + sA1, Bg1 + ko);
        }
        CP_COMMIT();

        const uint32_t stA = sbase + (kt % STAGES) * STAGE_BYTES;
        const uint32_t stB = stA + 8192;

#pragma unroll
        for (int k16 = 0; k16 < 2; k16++) {
            const int kc = k16 * 2;
            uint32_t af[2][4];
#pragma unroll
            for (int i = 0; i < 2; i++) {
                int r = aRow + i * 16;
                ldsm4(af[i][0], af[i][1], af[i][2], af[i][3],
                      stA + swz(r, kc + aCsel));
            }
            uint32_t bf[4][4];
#pragma unroll
            for (int j = 0; j < 4; j++) {
                int r = bRow + j * 16;
                ldsm4(bf[j][0], bf[j][1], bf[j][2], bf[j][3],
                      stB + swz(r, kc + bCsel));
            }
#pragma unroll
            for (int i = 0; i < 2; i++)
#pragma unroll
                for (int j = 0; j < 4; j++) {
                    mma16816(acc[i][2*j+0], af[i][0], af[i][1], af[i][2], af[i][3],
                             bf[j][0], bf[j][1]);
                    mma16816(acc[i][2*j+1], af[i][0], af[i][1], af[i][2], af[i][3],
                             bf[j][2], bf[j][3]);
                }
        }
    }

    const int gid = lane >> 2, q = lane & 3;
#pragma unroll
    for (int i = 0; i < 2; i++) {
        int r0 = m0 + wm * 32 + i * 16 + gid;
#pragma unroll
        for (int j = 0; j < 8; j++) {
            int col = n0 + wn * 64 + j * 8 + q * 2;
            *(float2*)(C + (size_t)r0 * cpitch + col) =
                make_float2(acc[i][j][0], acc[i][j][1]);
            *(float2*)(C + (size_t)(r0 + 8) * cpitch + col) =
                make_float2(acc[i][j][2], acc[i][j][3]);
        }
    }
}

// ---------------------------------------------------------------------------
// Flash attention, fp16 tensor cores. S: 3-term (Qhi Khi + Qlo Khi + Qhi Klo).
// PV: 2-term, P split hi/lo in registers, V single fp16 (transposed in smem).
// Warp = 16 q-rows x 128 keys. CTA = 256 thr = 8 warps = 128 q-rows.
// ---------------------------------------------------------------------------
#define A_QHI 0
#define A_QLO 16384
#define A_KHI 32768
#define A_KLO 49152
#define A_VT  65536
#define A_SMEM 81920

__global__ __launch_bounds__(256, 1)
void flash_attn_f16()
{
    extern __shared__ __align__(128) char smc[];
    const uint32_t sb = smem_u32(smc);
    const int tid  = threadIdx.x;
    const int lane = tid & 31;
    const int wid  = tid >> 5;
    const int gid  = lane >> 2;
    const int qq   = lane & 3;
    const int qt = blockIdx.x;
    const int h  = blockIdx.y;
    const int b  = blockIdx.z;
    const int q0 = qt * 128;

    // ---- fill Q hi/lo (scaled by 1/8), fp32 -> fp16 split -----------------
    const float* Qg = g_qkv + (size_t)(b * SEQ + q0) * K3 + h * D_HEAD;
#pragma unroll
    for (int it = 0; it < 4; it++) {
        int idx = tid + it * 256;
        int r = idx >> 3, c = idx & 7;
        const float* p = Qg + (size_t)r * K3 + c * 8;
        float4 u = *(const float4*)p;
        float4 v = *(const float4*)(p + 4);
        float f[8] = {u.x*0.125f, u.y*0.125f, u.z*0.125f, u.w*0.125f,
                      v.x*0.125f, v.y*0.125f, v.z*0.125f, v.w*0.125f};
        __half hi[8]; ushort lo[8]; ushort hib[8];
#pragma unroll
        for (int e = 0; e < 8; e++) {
            hi[e] = __float2half_rn(f[e]);
            hib[e] = __half_as_ushort(hi[e]);
            lo[e] = __half_as_ushort(__float2half_rn(f[e] - __half2float(hi[e])));
        }
        uint32_t off = swz128(r, c);
        *(uint4*)(smc + A_QHI + off) = *(uint4*)hib;
        *(uint4*)(smc + A_QLO + off) = *(uint4*)lo;
    }
    __syncthreads();

    // ---- load Q A-frags into registers ------------------------------------
    const int aRow = wid * 16 + (lane & 15);
    const int aCsel = lane >> 4;
    uint32_t qh[4][4], ql[4][4];
#pragma unroll
    for (int kt2 = 0; kt2 < 4; kt2++) {
        ldsm4(qh[kt2][0], qh[kt2][1], qh[kt2][2], qh[kt2][3],
              sb + A_QHI + swz128(aRow, kt2 * 2 + aCsel));
        ldsm4(ql[kt2][0], ql[kt2][1], ql[kt2][2], ql[kt2][3],
              sb + A_QLO + swz128(aRow, kt2 * 2 + aCsel));
    }

    float m0r = -1e30f, m1r = -1e30f, l0r = 0.f, l1r = 0.f;
    float oacc[8][4];
#pragma unroll
    for (int j = 0; j < 8; j++)
#pragma unroll
        for (int q2 = 0; q2 < 4; q2++) oacc[j][q2] = 0.f;

    const int bRowBase = (lane & 7) + ((lane >> 4) << 3);
    const int bCsel = (lane >> 3) & 1;
    const int row0 = wid * 16 + gid;      // local q row of c0,c1
    const int row1 = row0 + 8;            // local q row of c2,c3

    for (int t = 0; t <= qt; t++) {
        const int j0 = t * 128;
        __syncthreads();   // previous iteration's smem consumers done

        // ---- fill K hi/lo ---------------------------------------------------
        const float* Kg = g_qkv + (size_t)(b * SEQ + j0) * K3 + D_MODEL + h * D_HEAD;
#pragma unroll
        for (int it = 0; it < 4; it++) {
            int idx = tid + it * 256;
            int r = idx >> 3, c = idx & 7;
            const float* p = Kg + (size_t)r * K3 + c * 8;
            float4 u = *(const float4*)p;
            float4 v = *(const float4*)(p + 4);
            float f[8] = {u.x, u.y, u.z, u.w, v.x, v.y, v.z, v.w};
            ushort hib[8], lob[8];
#pragma unroll
            for (int e = 0; e < 8; e++) {
                __half hh = __float2half_rn(f[e]);
                hib[e] = __half_as_ushort(hh);
                lob[e] = __half_as_ushort(__float2half_rn(f[e] - __half2float(hh)));
            }
            uint32_t off = swz128(r, c);
            *(uint4*)(smc + A_KHI + off) = *(uint4*)hib;
            *(uint4*)(smc + A_KLO + off) = *(uint4*)lob;
        }
        // ---- fill V transposed (d-major), single fp16 ----------------------
        const float* Vg = g_qkv + (size_t)(b * SEQ + j0) * K3 + 2 * D_MODEL + h * D_HEAD;
#pragma unroll
        for (int it = 0; it < 4; it++) {
            int idx = tid + it * 256;
            int d = idx & 63, jc = idx >> 6;   // jc 0..15 (8 keys each)
            ushort vb[8];
#pragma unroll
            for (int jj = 0; jj < 8; jj++)
                vb[jj] = __half_as_ushort(
                    __float2half_rn(Vg[(size_t)(jc * 8 + jj) * K3 + d]));
            *(uint4*)(smc + A_VT + swzV(d, jc)) = *(uint4*)vb;
        }
        __syncthreads();

        // ---- S = Q K^T (3 fp16 terms) --------------------------------------
        float sacc[16][4];
#pragma unroll
        for (int j = 0; j < 16; j++)
#pragma unroll
            for (int q2 = 0; q2 < 4; q2++) sacc[j][q2] = 0.f;

#pragma unroll
        for (int kt2 = 0; kt2 < 4; kt2++) {
#pragma unroll
            for (int jt2 = 0; jt2 < 8; jt2++) {
                int r = jt2 * 16 + bRowBase;
                uint32_t kc = kt2 * 2 + bCsel;
                uint32_t bh[4], bl[4];
                ldsm4(bh[0], bh[1], bh[2], bh[3], sb + A_KHI + swz128(r, kc));
                ldsm4(bl[0], bl[1], bl[2], bl[3], sb + A_KLO + swz128(r, kc));
                mma16816h(sacc[2*jt2],   qh[kt2][0], qh[kt2][1], qh[kt2][2], qh[kt2][3], bh[0], bh[1]);
                mma16816h(sacc[2*jt2+1], qh[kt2][0], qh[kt2][1], qh[kt2][2], qh[kt2][3], bh[2], bh[3]);
                mma16816h(sacc[2*jt2],   ql[kt2][0], ql[kt2][1], ql[kt2][2], ql[kt2][3], bh[0], bh[1]);
                mma16816h(sacc[2*jt2+1], ql[kt2][0], ql[kt2][1], ql[kt2][2], ql[kt2][3], bh[2], bh[3]);
                mma16816h(sacc[2*jt2],   qh[kt2][0], qh[kt2][1], qh[kt2][2], qh[kt2][3], bl[0], bl[1]);
                mma16816h(sacc[2*jt2+1], qh[kt2][0], qh[kt2][1], qh[kt2][2], qh[kt2][3], bl[2], bl[3]);
            }
        }

        // ---- causal mask on diagonal tile ----------------------------------
        if (t == qt) {
#pragma unroll
            for (int j = 0; j < 16; j++) {
                int c0 = j * 8 + qq * 2;
                if (c0 > row0)     sacc[j][0] = -1e30f;
                if (c0 + 1 > row0) sacc[j][1] = -1e30f;
                if (c0 > row1)     sacc[j][2] = -1e30f;
                if (c0 + 1 > row1) sacc[j][3] = -1e30f;
            }
        }

        // ---- online softmax -------------------------------------------------
        float mx0 = -1e30f, mx1 = -1e30f;
#pragma unroll
        for (int j = 0; j < 16; j++) {
            mx0 = fmaxf(mx0, fmaxf(sacc[j][0], sacc[j][1]));
            mx1 = fmaxf(mx1, fmaxf(sacc[j][2], sacc[j][3]));
        }
        mx0 = fmaxf(mx0, __shfl_xor_sync(0xffffffffu, mx0, 1));
        mx0 = fmaxf(mx0, __shfl_xor_sync(0xffffffffu, mx0, 2));
        mx1 = fmaxf(mx1, __shfl_xor_sync(0xffffffffu, mx1, 1));
        mx1 = fmaxf(mx1, __shfl_xor_sync(0xffffffffu, mx1, 2));

        float mn0 = fmaxf(m0r, mx0), mn1 = fmaxf(m1r, mx1);
        float cr0 = __expf(m0r - mn0), cr1 = __expf(m1r - mn1);
        float sum0 = 0.f, sum1 = 0.f;
#pragma unroll
        for (int j = 0; j < 16; j++) {
            sacc[j][0] = __expf(sacc[j][0] - mn0);
            sacc[j][1] = __expf(sacc[j][1] - mn0);
            sacc[j][2] = __expf(sacc[j][2] - mn1);
            sacc[j][3] = __expf(sacc[j][3] - mn1);
            sum0 += sacc[j][0] + sacc[j][1];
            sum1 += sacc[j][2] + sacc[j][3];
        }
        sum0 += __shfl_xor_sync(0xffffffffu, sum0, 1);
        sum0 += __shfl_xor_sync(0xffffffffu, sum0, 2);
        sum1 += __shfl_xor_sync(0xffffffffu, sum1, 1);
        sum1 += __shfl_xor_sync(0xffffffffu, sum1, 2);

        l0r = l0r * cr0 + sum0;  m0r = mn0;
        l1r = l1r * cr1 + sum1;  m1r = mn1;
#pragma unroll
        for (int j = 0; j < 8; j++) {
            oacc[j][0] *= cr0; oacc[j][1] *= cr0;
            oacc[j][2] *= cr1; oacc[j][3] *= cr1;
        }

        // ---- O += P V (P split hi/lo from registers) -----------------------
#pragma unroll
        for (int kt2 = 0; kt2 < 8; kt2++) {
            const int jA = 2 * kt2, jB = 2 * kt2 + 1;
            uint32_t ph[4], pl[4];
            ph[0] = pack_h2(sacc[jA][0], sacc[jA][1]);
            ph[1] = pack_h2(sacc[jA][2], sacc[jA][3]);
            ph[2] = pack_h2(sacc[jB][0], sacc[jB][1]);
            ph[3] = pack_h2(sacc[jB][2], sacc[jB][3]);
            {
                __half2 h0 = *(__half2*)&ph[0];
                __half2 h1 = *(__half2*)&ph[1];
                __half2 h2 = *(__half2*)&ph[2];
                __half2 h3 = *(__half2*)&ph[3];
                pl[0] = pack_h2(sacc[jA][0] - __low2float(h0), sacc[jA][1] - __high2float(h0));
                pl[1] = pack_h2(sacc[jA][2] - __low2float(h1), sacc[jA][3] - __high2float(h1));
                pl[2] = pack_h2(sacc[jB][0] - __low2float(h2), sacc[jB][1] - __high2float(h2));
                pl[3] = pack_h2(sacc[jB][2] - __low2float(h3), sacc[jB][3] - __high2float(h3));
            }
#pragma unroll
            for (int nt2 = 0; nt2 < 4; nt2++) {
                int r = nt2 * 16 + bRowBase;
                uint32_t vc = kt2 * 2 + bCsel;
                uint32_t bv[4];
                ldsm4(bv[0], bv[1], bv[2], bv[3], sb + A_VT + swzV(r, vc));
                mma16816h(oacc[2*nt2],   ph[0], ph[1], ph[2], ph[3], bv[0], bv[1]);
                mma16816h(oacc[2*nt2+1], ph[0], ph[1], ph[2], ph[3], bv[2], bv[3]);
                mma16816h(oacc[2*nt2],   pl[0], pl[1], pl[2], pl[3], bv[0], bv[1]);
                mma16816h(oacc[2*nt2+1], pl[0], pl[1], pl[2], pl[3], bv[2], bv[3]);
            }
        }
    }

    // ---- normalize + store ------------------------------------------------
    const float inv0 = 1.0f / l0r, inv1 = 1.0f / l1r;
    const size_t gr0 = (size_t)(b * SEQ + q0 + row0);
    const size_t gr1 = (size_t)(b * SEQ + q0 + row1);
#pragma unroll
    for (int nt = 0; nt < 8; nt++) {
        int col = h * D_HEAD + nt * 8 + qq * 2;
        *(float2*)(g_ao + gr0 * D_MODEL + col) =
            make_float2(oacc[nt][0] * inv0, oacc[nt][1] * inv0);
        *(float2*)(g_ao + gr1 * D_MODEL + col) =
            make_float2(oacc[nt][2] * inv1, oacc[nt][3] * inv1);
    }
}

// ---------------------------------------------------------------------------
extern "C" void kernel_launch(void* const* d_in, const int* in_sizes, int n_in,
                              void* d_out, int out_size)
{
    const float* x  = (const float*)d_in[0];
    const float* Wq = (const float*)d_in[1];
    const float* Wk = (const float*)d_in[2];
    const float* Wv = (const float*)d_in[3];
    const float* Wo = (const float*)d_in[4];
    float* out = (float*)d_out;

    void *pqkv, *pa, *px2, *pa2, *pw2;
    cudaGetSymbolAddress(&pqkv, g_qkv);
    cudaGetSymbolAddress(&pa,   g_ao);
    cudaGetSymbolAddress(&px2,  g_x2);
    cudaGetSymbolAddress(&pa2,  g_ao2);
    cudaGetSymbolAddress(&pw2,  g_w2);

    __nv_bfloat16* x2  = (__nv_bfloat16*)px2;
    __nv_bfloat16* ao2 = (__nv_bfloat16*)pa2;
    __nv_bfloat16* w2  = (__nv_bfloat16*)pw2;

    cudaFuncSetAttribute(gemm_bf16,
                         cudaFuncAttributeMaxDynamicSharedMemorySize, G_SMEM);
    cudaFuncSetAttribute(flash_attn_f16,
                         cudaFuncAttributeMaxDynamicSharedMemorySize, A_SMEM);

    const int n4x = M_ROWS * D_MODEL / 4;
    const int n4w = D_MODEL * D_MODEL / 4;
    const size_t WSZ = (size_t)D_MODEL * K3;

    split3<<<(n4x + 255) / 256, 256>>>(x, x2, n4x, 2048, 1024);
    split3<<<(n4w + 255) / 256, 256>>>(Wq, w2 + 0 * WSZ, n4w, 1024, 2048);
    split3<<<(n4w + 255) / 256, 256>>>(Wk, w2 + 1 * WSZ, n4w, 1024, 2048);
    split3<<<(n4w + 255) / 256, 256>>>(Wv, w2 + 2 * WSZ, n4w, 1024, 2048);
    split3<<<(n4w + 255) / 256, 256>>>(Wo, w2 + 3 * WSZ, n4w, 1024, 2048);

    dim3 qkvgrid(K3 / BN, M_ROWS / BM);      // (24, 64)
    gemm_bf16<<<qkvgrid, 256, G_SMEM>>>(x2, w2, (float*)pqkv, K3);

    dim3 fgrid(SEQ / 128, N_HEADS, B_SZ);    // (16, 16, 4)
    flash_attn_f16<<<fgrid, 256, A_SMEM>>>();

    split3<<<(n4x + 255) / 256, 256>>>((const float*)pa, ao2, n4x, 2048, 1024);
    dim3 ogrid(D_MODEL / BN, M_ROWS / BM);   // (8, 64)
    gemm_bf16<<<ogrid, 256, G_SMEM>>>(ao2, w2 + 3 * WSZ, out, D_MODEL);
}

// round 6
// speedup vs baseline: 3.7141x; 1.2731x over previous
#include <cuda_runtime.h>
#include <cuda_fp16.h>
#include <cstdint>
#include <math.h>

#define D_MODEL 1024
#define N_HEADS 16
#define D_HEAD  64
#define B_SZ    4
#define SEQ     2048
#define M_ROWS  (B_SZ * SEQ)   // 8192
#define K3      (3 * D_MODEL)  // 3072
#define K2      (2 * D_MODEL)  // 2048 (hi|lo activation pitch)
#define WROW    D_MODEL        // weight row pitch (single fp16)

// ---------------- scratch (__device__ globals) ------------------------------
__device__ float  g_qkv[M_ROWS * K3];                 // fused q|k|v fp32
__device__ __half g_xh [M_ROWS * K2];                 // x  split  [hi | lo]
__device__ __half g_aoh[M_ROWS * K2];                 // attn out  [hi | lo]
__device__ __half g_wh [4 * D_MODEL * D_MODEL];       // Wq;Wk;Wv;Wo fp16

// ---------------- fp32 -> fp16 [hi|lo] split (pitch K2) ---------------------
__global__ void split2(const float* __restrict__ src, __half* __restrict__ dst, int n4)
{
    int i = blockIdx.x * 256 + threadIdx.x;
    if (i >= n4) return;
    int r = i >> 8;                 // 256 float4 per 1024-col row
    int c = (i & 255) * 4;
    float4 v = ((const float4*)src)[i];
    float f[4] = {v.x, v.y, v.z, v.w};
    ushort hb[4], lb[4];
#pragma unroll
    for (int e = 0; e < 4; e++) {
        __half hh = __float2half_rn(f[e]);
        hb[e] = __half_as_ushort(hh);
        lb[e] = __half_as_ushort(__float2half_rn(f[e] - __half2float(hh)));
    }
    size_t base = (size_t)r * K2 + c;
    *(ushort4*)(dst + base)           = *(ushort4*)hb;
    *(ushort4*)(dst + base + D_MODEL) = *(ushort4*)lb;
}

// ---------------- fp32 -> fp16 plain convert --------------------------------
__global__ void convh(const float* __restrict__ src, __half* __restrict__ dst, int n4)
{
    int i = blockIdx.x * 256 + threadIdx.x;
    if (i >= n4) return;
    float4 v = ((const float4*)src)[i];
    ushort hb[4] = {
        __half_as_ushort(__float2half_rn(v.x)),
        __half_as_ushort(__float2half_rn(v.y)),
        __half_as_ushort(__float2half_rn(v.z)),
        __half_as_ushort(__float2half_rn(v.w))};
    *(ushort4*)(dst + (size_t)i * 4) = *(ushort4*)hb;
}

// ---------------- common helpers --------------------------------------------
__device__ __forceinline__ uint32_t smem_u32(const void* p) {
    uint32_t a;
    asm("{ .reg .u64 t; cvta.to.shared.u64 t, %1; cvt.u32.u64 %0, t; }" : "=r"(a) : "l"(p));
    return a;
}
__device__ __forceinline__ void cp_async16(uint32_t s, const void* g) {
    asm volatile("cp.async.cg.shared.global [%0], [%1], 16;" :: "r"(s), "l"(g));
}
#define CP_COMMIT() asm volatile("cp.async.commit_group;" ::: "memory")
#define CP_WAIT1()  asm volatile("cp.async.wait_group 1;" ::: "memory")

__device__ __forceinline__ void ldsm4(uint32_t& r0, uint32_t& r1, uint32_t& r2, uint32_t& r3,
                                      uint32_t addr) {
    asm volatile("ldmatrix.sync.aligned.m8n8.x4.shared.b16 {%0,%1,%2,%3}, [%4];"
                 : "=r"(r0), "=r"(r1), "=r"(r2), "=r"(r3) : "r"(addr));
}
__device__ __forceinline__ void mma16816h(float* c, uint32_t a0, uint32_t a1,
                                          uint32_t a2, uint32_t a3,
                                          uint32_t b0, uint32_t b1) {
    asm volatile("mma.sync.aligned.m16n8k16.row.col.f32.f16.f16.f32 "
                 "{%0,%1,%2,%3}, {%4,%5,%6,%7}, {%8,%9}, {%0,%1,%2,%3};"
                 : "+f"(c[0]), "+f"(c[1]), "+f"(c[2]), "+f"(c[3])
                 : "r"(a0), "r"(a1), "r"(a2), "r"(a3), "r"(b0), "r"(b1));
}
__device__ __forceinline__ uint32_t swz(int row, int c) {          // 64B rows
    return (uint32_t)(row * 64 + ((c ^ ((row >> 1) & 3)) << 4));
}
__device__ __forceinline__ uint32_t swz128(int row, int c) {       // 128B rows
    return (uint32_t)(row * 128 + ((c ^ (row & 7)) << 4));
}
__device__ __forceinline__ uint32_t swzV(int row, int c) {         // 256B rows
    return (uint32_t)(row * 256 + ((c ^ (row & 7)) << 4));
}
__device__ __forceinline__ uint32_t pack_h2(float a, float b) {
    __half2 h = __floats2half2_rn(a, b);
    return *(uint32_t*)&h;
}

// ---------------- fp16 NT GEMM via mma.sync ---------------------------------
// C[m,n] = sum_{k<2048} A[m,k] * B[n, k & 1023]
// A: [M, 2048] fp16 (hi|lo). B: [N, 1024] fp16. fp32 accumulate.
#define BM 128
#define BN 128
#define BKT 32
#define STAGES 3
#define STAGE_BYTES 16384
#define G_SMEM (STAGES * STAGE_BYTES)
#define NKT (K2 / BKT)                 // 64

__global__ __launch_bounds__(256, 2)
void gemm_f16(const __half* __restrict__ A, const __half* __restrict__ B,
              float* __restrict__ C, int cpitch)
{
    extern __shared__ __align__(128) char sm[];
    const uint32_t sbase = smem_u32(sm);
    const int tid  = threadIdx.x;
    const int lane = tid & 31;
    const int wid  = tid >> 5;
    const int wm   = wid & 3;
    const int wn   = wid >> 2;
    const int m0 = blockIdx.y * BM;
    const int n0 = blockIdx.x * BN;

    const int lr0 = tid >> 2, lc0 = tid & 3;
    const int lr1 = (tid + 256) >> 2, lc1 = (tid + 256) & 3;

    const __half* Ag  = A + (size_t)(m0 + lr0) * K2 + lc0 * 8;
    const __half* Ag1 = A + (size_t)(m0 + lr1) * K2 + lc1 * 8;
    const __half* Bg  = B + (size_t)(n0 + lr0) * WROW + lc0 * 8;
    const __half* Bg1 = B + (size_t)(n0 + lr1) * WROW + lc1 * 8;
    const uint32_t sA0 = swz(lr0, lc0), sA1 = swz(lr1, lc1);

    float acc[2][8][4];
#pragma unroll
    for (int i = 0; i < 2; i++)
#pragma unroll
        for (int j = 0; j < 8; j++)
#pragma unroll
            for (int q = 0; q < 4; q++) acc[i][j][q] = 0.f;

#pragma unroll
    for (int s = 0; s < STAGES - 1; s++) {
        uint32_t st = sbase + s * STAGE_BYTES;
        int ko = s * BKT;
        cp_async16(st + sA0,        Ag  + ko);
        cp_async16(st + sA1,        Ag1 + ko);
        cp_async16(st + 8192 + sA0, Bg  + (ko & 1023));
        cp_async16(st + 8192 + sA1, Bg1 + (ko & 1023));
        CP_COMMIT();
    }

    const int aRow = wm * 32 + (lane & 15);
    const int aCsel = lane >> 4;
    const int bRow = wn * 64 + (lane & 7) + ((lane >> 4) << 3);
    const int bCsel = (lane >> 3) & 1;

    for (int kt = 0; kt < NKT; kt++) {
        CP_WAIT1();
        __syncthreads();

        if (kt + STAGES - 1 < NKT) {
            int s = (kt + STAGES - 1) % STAGES;
            int ko = (kt + STAGES - 1) * BKT;
            uint32_t st = sbase + s * STAGE_BYTES;
            cp_async16(st + sA0,        Ag  + ko);
            cp_async16(st + sA1,        Ag1 + ko);
            cp_async16(st + 8192 + sA0, Bg  + (ko & 1023));
            cp_async16(st + 8192 + sA1, Bg1 + (ko & 1023));
        }
        CP_COMMIT();

        const uint32_t stA = sbase + (kt % STAGES) * STAGE_BYTES;
        const uint32_t stB = stA + 8192;

#pragma unroll
        for (int k16 = 0; k16 < 2; k16++) {
            const int kc = k16 * 2;
            uint32_t af[2][4];
#pragma unroll
            for (int i = 0; i < 2; i++) {
                int r = aRow + i * 16;
                ldsm4(af[i][0], af[i][1], af[i][2], af[i][3],
                      stA + swz(r, kc + aCsel));
            }
            uint32_t bf[4][4];
#pragma unroll
            for (int j = 0; j < 4; j++) {
                int r = bRow + j * 16;
                ldsm4(bf[j][0], bf[j][1], bf[j][2], bf[j][3],
                      stB + swz(r, kc + bCsel));
            }
#pragma unroll
            for (int i = 0; i < 2; i++)
#pragma unroll
                for (int j = 0; j < 4; j++) {
                    mma16816h(acc[i][2*j+0], af[i][0], af[i][1], af[i][2], af[i][3],
                              bf[j][0], bf[j][1]);
                    mma16816h(acc[i][2*j+1], af[i][0], af[i][1], af[i][2], af[i][3],
                              bf[j][2], bf[j][3]);
                }
        }
    }

    const int gid = lane >> 2, q = lane & 3;
#pragma unroll
    for (int i = 0; i < 2; i++) {
        int r0 = m0 + wm * 32 + i * 16 + gid;
#pragma unroll
        for (int j = 0; j < 8; j++) {
            int col = n0 + wn * 64 + j * 8 + q * 2;
            *(float2*)(C + (size_t)r0 * cpitch + col) =
                make_float2(acc[i][j][0], acc[i][j][1]);
            *(float2*)(C + (size_t)(r0 + 8) * cpitch + col) =
                make_float2(acc[i][j][2], acc[i][j][3]);
        }
    }
}

// ---------------------------------------------------------------------------
// Flash attention, fp16 tensor cores (round-5 proven). Epilogue now writes
// the fp16 hi/lo split directly into g_aoh (pitch K2) — no fp32 round-trip.
// ---------------------------------------------------------------------------
#define A_QHI 0
#define A_QLO 16384
#define A_KHI 32768
#define A_KLO 49152
#define A_VT  65536
#define A_SMEM 81920

__global__ __launch_bounds__(256, 1)
void flash_attn_f16()
{
    extern __shared__ __align__(128) char smc[];
    const uint32_t sb = smem_u32(smc);
    const int tid  = threadIdx.x;
    const int lane = tid & 31;
    const int wid  = tid >> 5;
    const int gid  = lane >> 2;
    const int qq   = lane & 3;
    const int qt = blockIdx.x;
    const int h  = blockIdx.y;
    const int b  = blockIdx.z;
    const int q0 = qt * 128;

    const float* Qg = g_qkv + (size_t)(b * SEQ + q0) * K3 + h * D_HEAD;
#pragma unroll
    for (int it = 0; it < 4; it++) {
        int idx = tid + it * 256;
        int r = idx >> 3, c = idx & 7;
        const float* p = Qg + (size_t)r * K3 + c * 8;
        float4 u = *(const float4*)p;
        float4 v = *(const float4*)(p + 4);
        float f[8] = {u.x*0.125f, u.y*0.125f, u.z*0.125f, u.w*0.125f,
                      v.x*0.125f, v.y*0.125f, v.z*0.125f, v.w*0.125f};
        ushort hib[8], lob[8];
#pragma unroll
        for (int e = 0; e < 8; e++) {
            __half hh = __float2half_rn(f[e]);
            hib[e] = __half_as_ushort(hh);
            lob[e] = __half_as_ushort(__float2half_rn(f[e] - __half2float(hh)));
        }
        uint32_t off = swz128(r, c);
        *(uint4*)(smc + A_QHI + off) = *(uint4*)hib;
        *(uint4*)(smc + A_QLO + off) = *(uint4*)lob;
    }
    __syncthreads();

    const int aRow = wid * 16 + (lane & 15);
    const int aCsel = lane >> 4;
    uint32_t qh[4][4], ql[4][4];
#pragma unroll
    for (int kt2 = 0; kt2 < 4; kt2++) {
        ldsm4(qh[kt2][0], qh[kt2][1], qh[kt2][2], qh[kt2][3],
              sb + A_QHI + swz128(aRow, kt2 * 2 + aCsel));
        ldsm4(ql[kt2][0], ql[kt2][1], ql[kt2][2], ql[kt2][3],
              sb + A_QLO + swz128(aRow, kt2 * 2 + aCsel));
    }

    float m0r = -1e30f, m1r = -1e30f, l0r = 0.f, l1r = 0.f;
    float oacc[8][4];
#pragma unroll
    for (int j = 0; j < 8; j++)
#pragma unroll
        for (int q2 = 0; q2 < 4; q2++) oacc[j][q2] = 0.f;

    const int bRowBase = (lane & 7) + ((lane >> 4) << 3);
    const int bCsel = (lane >> 3) & 1;
    const int row0 = wid * 16 + gid;
    const int row1 = row0 + 8;

    for (int t = 0; t <= qt; t++) {
        const int j0 = t * 128;
        __syncthreads();

        const float* Kg = g_qkv + (size_t)(b * SEQ + j0) * K3 + D_MODEL + h * D_HEAD;
#pragma unroll
        for (int it = 0; it < 4; it++) {
            int idx = tid + it * 256;
            int r = idx >> 3, c = idx & 7;
            const float* p = Kg + (size_t)r * K3 + c * 8;
            float4 u = *(const float4*)p;
            float4 v = *(const float4*)(p + 4);
            float f[8] = {u.x, u.y, u.z, u.w, v.x, v.y, v.z, v.w};
            ushort hib[8], lob[8];
#pragma unroll
            for (int e = 0; e < 8; e++) {
                __half hh = __float2half_rn(f[e]);
                hib[e] = __half_as_ushort(hh);
                lob[e] = __half_as_ushort(__float2half_rn(f[e] - __half2float(hh)));
            }
            uint32_t off = swz128(r, c);
            *(uint4*)(smc + A_KHI + off) = *(uint4*)hib;
            *(uint4*)(smc + A_KLO + off) = *(uint4*)lob;
        }
        const float* Vg = g_qkv + (size_t)(b * SEQ + j0) * K3 + 2 * D_MODEL + h * D_HEAD;
#pragma unroll
        for (int it = 0; it < 4; it++) {
            int idx = tid + it * 256;
            int d = idx & 63, jc = idx >> 6;
            ushort vb[8];
#pragma unroll
            for (int jj = 0; jj < 8; jj++)
                vb[jj] = __half_as_ushort(
                    __float2half_rn(Vg[(size_t)(jc * 8 + jj) * K3 + d]));
            *(uint4*)(smc + A_VT + swzV(d, jc)) = *(uint4*)vb;
        }
        __syncthreads();

        float sacc[16][4];
#pragma unroll
        for (int j = 0; j < 16; j++)
#pragma unroll
            for (int q2 = 0; q2 < 4; q2++) sacc[j][q2] = 0.f;

#pragma unroll
        for (int kt2 = 0; kt2 < 4; kt2++) {
#pragma unroll
            for (int jt2 = 0; jt2 < 8; jt2++) {
                int r = jt2 * 16 + bRowBase;
                uint32_t kc = kt2 * 2 + bCsel;
                uint32_t bh[4], bl[4];
                ldsm4(bh[0], bh[1], bh[2], bh[3], sb + A_KHI + swz128(r, kc));
                ldsm4(bl[0], bl[1], bl[2], bl[3], sb + A_KLO + swz128(r, kc));
                mma16816h(sacc[2*jt2],   qh[kt2][0], qh[kt2][1], qh[kt2][2], qh[kt2][3], bh[0], bh[1]);
                mma16816h(sacc[2*jt2+1], qh[kt2][0], qh[kt2][1], qh[kt2][2], qh[kt2][3], bh[2], bh[3]);
                mma16816h(sacc[2*jt2],   ql[kt2][0], ql[kt2][1], ql[kt2][2], ql[kt2][3], bh[0], bh[1]);
                mma16816h(sacc[2*jt2+1], ql[kt2][0], ql[kt2][1], ql[kt2][2], ql[kt2][3], bh[2], bh[3]);
                mma16816h(sacc[2*jt2],   qh[kt2][0], qh[kt2][1], qh[kt2][2], qh[kt2][3], bl[0], bl[1]);
                mma16816h(sacc[2*jt2+1], qh[kt2][0], qh[kt2][1], qh[kt2][2], qh[kt2][3], bl[2], bl[3]);
            }
        }

        if (t == qt) {
#pragma unroll
            for (int j = 0; j < 16; j++) {
                int c0 = j * 8 + qq * 2;
                if (c0 > row0)     sacc[j][0] = -1e30f;
                if (c0 + 1 > row0) sacc[j][1] = -1e30f;
                if (c0 > row1)     sacc[j][2] = -1e30f;
                if (c0 + 1 > row1) sacc[j][3] = -1e30f;
            }
        }

        float mx0 = -1e30f, mx1 = -1e30f;
#pragma unroll
        for (int j = 0; j < 16; j++) {
            mx0 = fmaxf(mx0, fmaxf(sacc[j][0], sacc[j][1]));
            mx1 = fmaxf(mx1, fmaxf(sacc[j][2], sacc[j][3]));
        }
        mx0 = fmaxf(mx0, __shfl_xor_sync(0xffffffffu, mx0, 1));
        mx0 = fmaxf(mx0, __shfl_xor_sync(0xffffffffu, mx0, 2));
        mx1 = fmaxf(mx1, __shfl_xor_sync(0xffffffffu, mx1, 1));
        mx1 = fmaxf(mx1, __shfl_xor_sync(0xffffffffu, mx1, 2));

        float mn0 = fmaxf(m0r, mx0), mn1 = fmaxf(m1r, mx1);
        float cr0 = __expf(m0r - mn0), cr1 = __expf(m1r - mn1);
        float sum0 = 0.f, sum1 = 0.f;
#pragma unroll
        for (int j = 0; j < 16; j++) {
            sacc[j][0] = __expf(sacc[j][0] - mn0);
            sacc[j][1] = __expf(sacc[j][1] - mn0);
            sacc[j][2] = __expf(sacc[j][2] - mn1);
            sacc[j][3] = __expf(sacc[j][3] - mn1);
            sum0 += sacc[j][0] + sacc[j][1];
            sum1 += sacc[j][2] + sacc[j][3];
        }
        sum0 += __shfl_xor_sync(0xffffffffu, sum0, 1);
        sum0 += __shfl_xor_sync(0xffffffffu, sum0, 2);
        sum1 += __shfl_xor_sync(0xffffffffu, sum1, 1);
        sum1 += __shfl_xor_sync(0xffffffffu, sum1, 2);

        l0r = l0r * cr0 + sum0;  m0r = mn0;
        l1r = l1r * cr1 + sum1;  m1r = mn1;
#pragma unroll
        for (int j = 0; j < 8; j++) {
            oacc[j][0] *= cr0; oacc[j][1] *= cr0;
            oacc[j][2] *= cr1; oacc[j][3] *= cr1;
        }

#pragma unroll
        for (int kt2 = 0; kt2 < 8; kt2++) {
            const int jA = 2 * kt2, jB = 2 * kt2 + 1;
            uint32_t ph[4], pl[4];
            ph[0] = pack_h2(sacc[jA][0], sacc[jA][1]);
            ph[1] = pack_h2(sacc[jA][2], sacc[jA][3]);
            ph[2] = pack_h2(sacc[jB][0], sacc[jB][1]);
            ph[3] = pack_h2(sacc[jB][2], sacc[jB][3]);
            {
                __half2 h0 = *(__half2*)&ph[0];
                __half2 h1 = *(__half2*)&ph[1];
                __half2 h2 = *(__half2*)&ph[2];
                __half2 h3 = *(__half2*)&ph[3];
                pl[0] = pack_h2(sacc[jA][0] - __low2float(h0), sacc[jA][1] - __high2float(h0));
                pl[1] = pack_h2(sacc[jA][2] - __low2float(h1), sacc[jA][3] - __high2float(h1));
                pl[2] = pack_h2(sacc[jB][0] - __low2float(h2), sacc[jB][1] - __high2float(h2));
                pl[3] = pack_h2(sacc[jB][2] - __low2float(h3), sacc[jB][3] - __high2float(h3));
            }
#pragma unroll
            for (int nt2 = 0; nt2 < 4; nt2++) {
                int r = nt2 * 16 + bRowBase;
                uint32_t vc = kt2 * 2 + bCsel;
                uint32_t bv[4];
                ldsm4(bv[0], bv[1], bv[2], bv[3], sb + A_VT + swzV(r, vc));
                mma16816h(oacc[2*nt2],   ph[0], ph[1], ph[2], ph[3], bv[0], bv[1]);
                mma16816h(oacc[2*nt2+1], ph[0], ph[1], ph[2], ph[3], bv[2], bv[3]);
                mma16816h(oacc[2*nt2],   pl[0], pl[1], pl[2], pl[3], bv[0], bv[1]);
                mma16816h(oacc[2*nt2+1], pl[0], pl[1], pl[2], pl[3], bv[2], bv[3]);
            }
        }
    }

    // ---- normalize + store fp16 hi/lo split directly ----------------------
    const float inv0 = 1.0f / l0r, inv1 = 1.0f / l1r;
    const size_t gr0 = (size_t)(b * SEQ + q0 + row0);
    const size_t gr1 = (size_t)(b * SEQ + q0 + row1);
#pragma unroll
    for (int nt = 0; nt < 8; nt++) {
        int col = h * D_HEAD + nt * 8 + qq * 2;
        float a0 = oacc[nt][0] * inv0, a1 = oacc[nt][1] * inv0;
        float b0f = oacc[nt][2] * inv1, b1f = oacc[nt][3] * inv1;
        uint32_t h0 = pack_h2(a0, a1), h1 = pack_h2(b0f, b1f);
        __half2 hh0 = *(__half2*)&h0, hh1 = *(__half2*)&h1;
        uint32_t l0 = pack_h2(a0 - __low2float(hh0), a1 - __high2float(hh0));
        uint32_t l1 = pack_h2(b0f - __low2float(hh1), b1f - __high2float(hh1));
        *(uint32_t*)(g_aoh + gr0 * K2 + col)           = h0;
        *(uint32_t*)(g_aoh + gr0 * K2 + D_MODEL + col) = l0;
        *(uint32_t*)(g_aoh + gr1 * K2 + col)           = h1;
        *(uint32_t*)(g_aoh + gr1 * K2 + D_MODEL + col) = l1;
    }
}

// ---------------------------------------------------------------------------
extern "C" void kernel_launch(void* const* d_in, const int* in_sizes, int n_in,
                              void* d_out, int out_size)
{
    const float* x  = (const float*)d_in[0];
    const float* Wq = (const float*)d_in[1];
    const float* Wk = (const float*)d_in[2];
    const float* Wv = (const float*)d_in[3];
    const float* Wo = (const float*)d_in[4];
    float* out = (float*)d_out;

    void *pqkv, *pxh, *paoh, *pwh;
    cudaGetSymbolAddress(&pqkv, g_qkv);
    cudaGetSymbolAddress(&pxh,  g_xh);
    cudaGetSymbolAddress(&paoh, g_aoh);
    cudaGetSymbolAddress(&pwh,  g_wh);

    __half* xh  = (__half*)pxh;
    __half* aoh = (__half*)paoh;
    __half* wh  = (__half*)pwh;

    cudaFuncSetAttribute(gemm_f16,
                         cudaFuncAttributeMaxDynamicSharedMemorySize, G_SMEM);
    cudaFuncSetAttribute(flash_attn_f16,
                         cudaFuncAttributeMaxDynamicSharedMemorySize, A_SMEM);

    const int n4x = M_ROWS * D_MODEL / 4;
    const int n4w = D_MODEL * D_MODEL / 4;
    const size_t WSZ = (size_t)D_MODEL * D_MODEL;

    split2<<<(n4x + 255) / 256, 256>>>(x, xh, n4x);
    convh <<<(n4w + 255) / 256, 256>>>(Wq, wh + 0 * WSZ, n4w);
    convh <<<(n4w + 255) / 256, 256>>>(Wk, wh + 1 * WSZ, n4w);
    convh <<<(n4w + 255) / 256, 256>>>(Wv, wh + 2 * WSZ, n4w);
    convh <<<(n4w + 255) / 256, 256>>>(Wo, wh + 3 * WSZ, n4w);

    // Fused QKV GEMM: B = [Wq;Wk;Wv] rows 0..3071, N=3072
    dim3 qkvgrid(K3 / BN, M_ROWS / BM);      // (24, 64)
    gemm_f16<<<qkvgrid, 256, G_SMEM>>>(xh, wh, (float*)pqkv, K3);

    dim3 fgrid(SEQ / 128, N_HEADS, B_SZ);    // (16, 16, 4)
    flash_attn_f16<<<fgrid, 256, A_SMEM>>>();

    dim3 ogrid(D_MODEL / BN, M_ROWS / BM);   // (8, 64)
    gemm_f16<<<ogrid, 256, G_SMEM>>>(aoh, wh + 3 * WSZ, out, D_MODEL);
}

// round 7
// speedup vs baseline: 3.8478x; 1.0360x over previous
#include <cuda_runtime.h>
#include <cuda_fp16.h>
#include <cstdint>
#include <math.h>

#define D_MODEL 1024
#define N_HEADS 16
#define D_HEAD  64
#define B_SZ    4
#define SEQ     2048
#define M_ROWS  (B_SZ * SEQ)   // 8192
#define K3      (3 * D_MODEL)  // 3072
#define K2      (2 * D_MODEL)  // 2048
#define WROW    D_MODEL
#define NQT     (SEQ / 128)    // 16 tiles per (b,h)

// ---------------- scratch (__device__ globals) ------------------------------
__device__ float  g_qkv[M_ROWS * K3];                 // fused q|k|v fp32
__device__ __half g_xh [M_ROWS * K2];                 // x split [hi | lo]
__device__ __half g_aoh[M_ROWS * K2];                 // attn out split [hi | lo]
__device__ __half g_wh [4 * D_MODEL * D_MODEL];       // weights fp16

// Pre-swizzled fp16 tile images (exact smem byte layout):
//  Qp per (b,h,tile): [QHI 16KB][QLO 16KB]            = 32KB
//  KVp per (b,h,tile): [KHI 16KB][KLO 16KB][VT 16KB]  = 48KB
__device__ __half g_Qp [B_SZ * N_HEADS * NQT * 16384];   // 32 MB
__device__ __half g_KVp[B_SZ * N_HEADS * NQT * 24576];   // 48 MB

// ---------------- helpers ----------------------------------------------------
__device__ __forceinline__ uint32_t smem_u32(const void* p) {
    uint32_t a;
    asm("{ .reg .u64 t; cvta.to.shared.u64 t, %1; cvt.u32.u64 %0, t; }" : "=r"(a) : "l"(p));
    return a;
}
__device__ __forceinline__ void cp_async16(uint32_t s, const void* g) {
    asm volatile("cp.async.cg.shared.global [%0], [%1], 16;" :: "r"(s), "l"(g));
}
#define CP_COMMIT() asm volatile("cp.async.commit_group;" ::: "memory")
#define CP_WAIT0()  asm volatile("cp.async.wait_group 0;" ::: "memory")
#define CP_WAIT1()  asm volatile("cp.async.wait_group 1;" ::: "memory")

__device__ __forceinline__ void ldsm4(uint32_t& r0, uint32_t& r1, uint32_t& r2, uint32_t& r3,
                                      uint32_t addr) {
    asm volatile("ldmatrix.sync.aligned.m8n8.x4.shared.b16 {%0,%1,%2,%3}, [%4];"
                 : "=r"(r0), "=r"(r1), "=r"(r2), "=r"(r3) : "r"(addr));
}
__device__ __forceinline__ void mma16816h(float* c, uint32_t a0, uint32_t a1,
                                          uint32_t a2, uint32_t a3,
                                          uint32_t b0, uint32_t b1) {
    asm volatile("mma.sync.aligned.m16n8k16.row.col.f32.f16.f16.f32 "
                 "{%0,%1,%2,%3}, {%4,%5,%6,%7}, {%8,%9}, {%0,%1,%2,%3};"
                 : "+f"(c[0]), "+f"(c[1]), "+f"(c[2]), "+f"(c[3])
                 : "r"(a0), "r"(a1), "r"(a2), "r"(a3), "r"(b0), "r"(b1));
}
__device__ __forceinline__ uint32_t swz(int row, int c) {          // 64B rows
    return (uint32_t)(row * 64 + ((c ^ ((row >> 1) & 3)) << 4));
}
__device__ __forceinline__ uint32_t swz128(int row, int c) {       // 128B rows
    return (uint32_t)(row * 128 + ((c ^ (row & 7)) << 4));
}
__device__ __forceinline__ uint32_t swzV(int row, int c) {         // 256B rows
    return (uint32_t)(row * 256 + ((c ^ (row & 7)) << 4));
}
__device__ __forceinline__ uint32_t pack_h2(float a, float b) {
    __half2 h = __floats2half2_rn(a, b);
    return *(uint32_t*)&h;
}

// ---------------- fp32 -> fp16 [hi|lo] split (pitch K2) ----------------------
__global__ void split2(const float* __restrict__ src, __half* __restrict__ dst, int n4)
{
    int i = blockIdx.x * 256 + threadIdx.x;
    if (i >= n4) return;
    int r = i >> 8;
    int c = (i & 255) * 4;
    float4 v = ((const float4*)src)[i];
    float f[4] = {v.x, v.y, v.z, v.w};
    ushort hb[4], lb[4];
#pragma unroll
    for (int e = 0; e < 4; e++) {
        __half hh = __float2half_rn(f[e]);
        hb[e] = __half_as_ushort(hh);
        lb[e] = __half_as_ushort(__float2half_rn(f[e] - __half2float(hh)));
    }
    size_t base = (size_t)r * K2 + c;
    *(ushort4*)(dst + base)           = *(ushort4*)hb;
    *(ushort4*)(dst + base + D_MODEL) = *(ushort4*)lb;
}

// ---------------- 4 weights fp32 -> fp16, one launch -------------------------
__global__ void convh4(const float* __restrict__ w0, const float* __restrict__ w1,
                       const float* __restrict__ w2, const float* __restrict__ w3,
                       __half* __restrict__ dst, int n4)
{
    int i = blockIdx.x * 256 + threadIdx.x;
    if (i >= n4) return;
    const float* srcs[4] = {w0, w1, w2, w3};
    const float* src = srcs[blockIdx.y];
    __half* d = dst + (size_t)blockIdx.y * D_MODEL * D_MODEL;
    float4 v = ((const float4*)src)[i];
    ushort hb[4] = {
        __half_as_ushort(__float2half_rn(v.x)),
        __half_as_ushort(__float2half_rn(v.y)),
        __half_as_ushort(__float2half_rn(v.z)),
        __half_as_ushort(__float2half_rn(v.w))};
    *(ushort4*)(d + (size_t)i * 4) = *(ushort4*)hb;
}

// ---------------- fp16 NT GEMM (round-6 proven) ------------------------------
#define BM 128
#define BN 128
#define BKT 32
#define STAGES 3
#define STAGE_BYTES 16384
#define G_SMEM (STAGES * STAGE_BYTES)
#define NKT (K2 / BKT)

__global__ __launch_bounds__(256, 2)
void gemm_f16(const __half* __restrict__ A, const __half* __restrict__ B,
              float* __restrict__ C, int cpitch)
{
    extern __shared__ __align__(128) char sm[];
    const uint32_t sbase = smem_u32(sm);
    const int tid  = threadIdx.x;
    const int lane = tid & 31;
    const int wid  = tid >> 5;
    const int wm   = wid & 3;
    const int wn   = wid >> 2;
    const int m0 = blockIdx.y * BM;
    const int n0 = blockIdx.x * BN;

    const int lr0 = tid >> 2, lc0 = tid & 3;
    const int lr1 = (tid + 256) >> 2, lc1 = (tid + 256) & 3;

    const __half* Ag  = A + (size_t)(m0 + lr0) * K2 + lc0 * 8;
    const __half* Ag1 = A + (size_t)(m0 + lr1) * K2 + lc1 * 8;
    const __half* Bg  = B + (size_t)(n0 + lr0) * WROW + lc0 * 8;
    const __half* Bg1 = B + (size_t)(n0 + lr1) * WROW + lc1 * 8;
    const uint32_t sA0 = swz(lr0, lc0), sA1 = swz(lr1, lc1);

    float acc[2][8][4];
#pragma unroll
    for (int i = 0; i < 2; i++)
#pragma unroll
        for (int j = 0; j < 8; j++)
#pragma unroll
            for (int q = 0; q < 4; q++) acc[i][j][q] = 0.f;

#pragma unroll
    for (int s = 0; s < STAGES - 1; s++) {
        uint32_t st = sbase + s * STAGE_BYTES;
        int ko = s * BKT;
        cp_async16(st + sA0,        Ag  + ko);
        cp_async16(st + sA1,        Ag1 + ko);
        cp_async16(st + 8192 + sA0, Bg  + (ko & 1023));
        cp_async16(st + 8192 + sA1, Bg1 + (ko & 1023));
        CP_COMMIT();
    }

    const int aRow = wm * 32 + (lane & 15);
    const int aCsel = lane >> 4;
    const int bRow = wn * 64 + (lane & 7) + ((lane >> 4) << 3);
    const int bCsel = (lane >> 3) & 1;

    for (int kt = 0; kt < NKT; kt++) {
        CP_WAIT1();
        __syncthreads();

        if (kt + STAGES - 1 < NKT) {
            int s = (kt + STAGES - 1) % STAGES;
            int ko = (kt + STAGES - 1) * BKT;
            uint32_t st = sbase + s * STAGE_BYTES;
            cp_async16(st + sA0,        Ag  + ko);
            cp_async16(st + sA1,        Ag1 + ko);
            cp_async16(st + 8192 + sA0, Bg  + (ko & 1023));
            cp_async16(st + 8192 + sA1, Bg1 + (ko & 1023));
        }
        CP_COMMIT();

        const uint32_t stA = sbase + (kt % STAGES) * STAGE_BYTES;
        const uint32_t stB = stA + 8192;

#pragma unroll
        for (int k16 = 0; k16 < 2; k16++) {
            const int kc = k16 * 2;
            uint32_t af[2][4];
#pragma unroll
            for (int i = 0; i < 2; i++) {
                int r = aRow + i * 16;
                ldsm4(af[i][0], af[i][1], af[i][2], af[i][3],
                      stA + swz(r, kc + aCsel));
            }
            uint32_t bf[4][4];
#pragma unroll
            for (int j = 0; j < 4; j++) {
                int r = bRow + j * 16;
                ldsm4(bf[j][0], bf[j][1], bf[j][2], bf[j][3],
                      stB + swz(r, kc + bCsel));
            }
#pragma unroll
            for (int i = 0; i < 2; i++)
#pragma unroll
                for (int j = 0; j < 4; j++) {
                    mma16816h(acc[i][2*j+0], af[i][0], af[i][1], af[i][2], af[i][3],
                              bf[j][0], bf[j][1]);
                    mma16816h(acc[i][2*j+1], af[i][0], af[i][1], af[i][2], af[i][3],
                              bf[j][2], bf[j][3]);
                }
        }
    }

    const int gid = lane >> 2, q = lane & 3;
#pragma unroll
    for (int i = 0; i < 2; i++) {
        int r0 = m0 + wm * 32 + i * 16 + gid;
#pragma unroll
        for (int j = 0; j < 8; j++) {
            int col = n0 + wn * 64 + j * 8 + q * 2;
            *(float2*)(C + (size_t)r0 * cpitch + col) =
                make_float2(acc[i][j][0], acc[i][j][1]);
            *(float2*)(C + (size_t)(r0 + 8) * cpitch + col) =
                make_float2(acc[i][j][2], acc[i][j][3]);
        }
    }
}

// ---------------------------------------------------------------------------
// prep: fp32 qkv -> pre-swizzled fp16 tile images (Q scaled+split, K split,
// V transposed). One CTA per (tile, head, batch); done ONCE per tile.
// ---------------------------------------------------------------------------
__global__ __launch_bounds__(256, 4)
void prep_attn()
{
    const int tid = threadIdx.x;
    const int t = blockIdx.x, h = blockIdx.y, b = blockIdx.z;
    const int r0 = t * 128;
    const size_t bh = (size_t)(b * N_HEADS + h) * NQT + t;

    char* qdst  = (char*)(g_Qp  + bh * 16384);
    char* kvdst = (char*)(g_KVp + bh * 24576);

    // Q (scale 1/8) and K: hi/lo split, swz128 images
    const float* Qg = g_qkv + (size_t)(b * SEQ + r0) * K3 + h * D_HEAD;
    const float* Kg = Qg + D_MODEL;
#pragma unroll
    for (int it = 0; it < 4; it++) {
        int idx = tid + it * 256;
        int r = idx >> 3, c = idx & 7;
        uint32_t off = swz128(r, c);
        {
            const float* p = Qg + (size_t)r * K3 + c * 8;
            float4 u = *(const float4*)p;
            float4 v = *(const float4*)(p + 4);
            float f[8] = {u.x*0.125f, u.y*0.125f, u.z*0.125f, u.w*0.125f,
                          v.x*0.125f, v.y*0.125f, v.z*0.125f, v.w*0.125f};
            ushort hib[8], lob[8];
#pragma unroll
            for (int e = 0; e < 8; e++) {
                __half hh = __float2half_rn(f[e]);
                hib[e] = __half_as_ushort(hh);
                lob[e] = __half_as_ushort(__float2half_rn(f[e] - __half2float(hh)));
            }
            *(uint4*)(qdst + off)         = *(uint4*)hib;
            *(uint4*)(qdst + 16384 + off) = *(uint4*)lob;
        }
        {
            const float* p = Kg + (size_t)r * K3 + c * 8;
            float4 u = *(const float4*)p;
            float4 v = *(const float4*)(p + 4);
            float f[8] = {u.x, u.y, u.z, u.w, v.x, v.y, v.z, v.w};
            ushort hib[8], lob[8];
#pragma unroll
            for (int e = 0; e < 8; e++) {
                __half hh = __float2half_rn(f[e]);
                hib[e] = __half_as_ushort(hh);
                lob[e] = __half_as_ushort(__float2half_rn(f[e] - __half2float(hh)));
            }
            *(uint4*)(kvdst + off)         = *(uint4*)hib;
            *(uint4*)(kvdst + 16384 + off) = *(uint4*)lob;
        }
    }
    // V transposed: swzV image (64 d-rows x 256B)
    const float* Vg = Qg + 2 * D_MODEL;
#pragma unroll
    for (int it = 0; it < 4; it++) {
        int idx = tid + it * 256;
        int d = idx & 63, jc = idx >> 6;
        ushort vb[8];
#pragma unroll
        for (int jj = 0; jj < 8; jj++)
            vb[jj] = __half_as_ushort(
                __float2half_rn(Vg[(size_t)(jc * 8 + jj) * K3 + d]));
        *(uint4*)(kvdst + 32768 + swzV(d, jc)) = *(uint4*)vb;
    }
}

// ---------------------------------------------------------------------------
// Flash attention: pure cp.async + ldsm + HMMA. Q resident, K/V double-buffered.
// ---------------------------------------------------------------------------
#define SM_Q   0                      // 32 KB (QHI | QLO)
#define SM_ST  32768                  // stage base
#define STG    49152                  // per-stage: KHI | KLO | VT
#define A_SMEM (32768 + 2 * 49152)    // 131072

__global__ __launch_bounds__(256, 1)
void flash_attn_f16()
{
    extern __shared__ __align__(128) char smc[];
    const uint32_t sb = smem_u32(smc);
    const int tid  = threadIdx.x;
    const int lane = tid & 31;
    const int wid  = tid >> 5;
    const int gid  = lane >> 2;
    const int qq   = lane & 3;
    const int qt = gridDim.x - 1 - blockIdx.x;   // heavy tiles first
    const int h  = blockIdx.y;
    const int b  = blockIdx.z;
    const int q0 = qt * 128;
    const size_t bhbase = (size_t)(b * N_HEADS + h) * NQT;

    // prologue: Q + tile0 in one group
    {
        const char* qs = (const char*)(g_Qp + (bhbase + qt) * 16384);
#pragma unroll
        for (int i = 0; i < 8; i++) {
            uint32_t off = (tid + i * 256) * 16;
            cp_async16(sb + SM_Q + off, qs + off);
        }
        const char* kvs = (const char*)(g_KVp + bhbase * 24576);
#pragma unroll
        for (int i = 0; i < 12; i++) {
            uint32_t off = (tid + i * 256) * 16;
            cp_async16(sb + SM_ST + off, kvs + off);
        }
        CP_COMMIT();
    }
    CP_WAIT0();
    __syncthreads();

    // Q fragments (resident in registers)
    const int aRow = wid * 16 + (lane & 15);
    const int aCsel = lane >> 4;
    uint32_t qh[4][4], ql[4][4];
#pragma unroll
    for (int kt2 = 0; kt2 < 4; kt2++) {
        ldsm4(qh[kt2][0], qh[kt2][1], qh[kt2][2], qh[kt2][3],
              sb + SM_Q + swz128(aRow, kt2 * 2 + aCsel));
        ldsm4(ql[kt2][0], ql[kt2][1], ql[kt2][2], ql[kt2][3],
              sb + SM_Q + 16384 + swz128(aRow, kt2 * 2 + aCsel));
    }

    float m0r = -1e30f, m1r = -1e30f, l0r = 0.f, l1r = 0.f;
    float oacc[8][4];
#pragma unroll
    for (int j = 0; j < 8; j++)
#pragma unroll
        for (int q2 = 0; q2 < 4; q2++) oacc[j][q2] = 0.f;

    const int bRowBase = (lane & 7) + ((lane >> 4) << 3);
    const int bCsel = (lane >> 3) & 1;
    const int row0 = wid * 16 + gid;
    const int row1 = row0 + 8;

    for (int t = 0; t <= qt; t++) {
        if (t > 0) {                    // tile t arrived? (issued at iter t-1)
            CP_WAIT0();
            __syncthreads();            // also: all compute on buffer (t&1) done
        }
        if (t < qt) {                   // prefetch tile t+1 into other buffer
            const char* kvs = (const char*)(g_KVp + (bhbase + t + 1) * 24576);
            uint32_t dst = sb + SM_ST + ((t + 1) & 1) * STG;
#pragma unroll
            for (int i = 0; i < 12; i++) {
                uint32_t off = (tid + i * 256) * 16;
                cp_async16(dst + off, kvs + off);
            }
            CP_COMMIT();
        }

        const uint32_t kb = sb + SM_ST + (t & 1) * STG;   // KHI
        const uint32_t lb = kb + 16384;                   // KLO
        const uint32_t vb = kb + 32768;                   // VT

        // ---- S = Q K^T (3 fp16 terms) ----
        float sacc[16][4];
#pragma unroll
        for (int j = 0; j < 16; j++)
#pragma unroll
            for (int q2 = 0; q2 < 4; q2++) sacc[j][q2] = 0.f;

#pragma unroll
        for (int kt2 = 0; kt2 < 4; kt2++) {
#pragma unroll
            for (int jt2 = 0; jt2 < 8; jt2++) {
                int r = jt2 * 16 + bRowBase;
                uint32_t kc = kt2 * 2 + bCsel;
                uint32_t bh4[4], bl4[4];
                ldsm4(bh4[0], bh4[1], bh4[2], bh4[3], kb + swz128(r, kc));
                ldsm4(bl4[0], bl4[1], bl4[2], bl4[3], lb + swz128(r, kc));
                mma16816h(sacc[2*jt2],   qh[kt2][0], qh[kt2][1], qh[kt2][2], qh[kt2][3], bh4[0], bh4[1]);
                mma16816h(sacc[2*jt2+1], qh[kt2][0], qh[kt2][1], qh[kt2][2], qh[kt2][3], bh4[2], bh4[3]);
                mma16816h(sacc[2*jt2],   ql[kt2][0], ql[kt2][1], ql[kt2][2], ql[kt2][3], bh4[0], bh4[1]);
                mma16816h(sacc[2*jt2+1], ql[kt2][0], ql[kt2][1], ql[kt2][2], ql[kt2][3], bh4[2], bh4[3]);
                mma16816h(sacc[2*jt2],   qh[kt2][0], qh[kt2][1], qh[kt2][2], qh[kt2][3], bl4[0], bl4[1]);
                mma16816h(sacc[2*jt2+1], qh[kt2][0], qh[kt2][1], qh[kt2][2], qh[kt2][3], bl4[2], bl4[3]);
            }
        }

        if (t == qt) {
#pragma unroll
            for (int j = 0; j < 16; j++) {
                int c0 = j * 8 + qq * 2;
                if (c0 > row0)     sacc[j][0] = -1e30f;
                if (c0 + 1 > row0) sacc[j][1] = -1e30f;
                if (c0 > row1)     sacc[j][2] = -1e30f;
                if (c0 + 1 > row1) sacc[j][3] = -1e30f;
            }
        }

        // ---- online softmax ----
        float mx0 = -1e30f, mx1 = -1e30f;
#pragma unroll
        for (int j = 0; j < 16; j++) {
            mx0 = fmaxf(mx0, fmaxf(sacc[j][0], sacc[j][1]));
            mx1 = fmaxf(mx1, fmaxf(sacc[j][2], sacc[j][3]));
        }
        mx0 = fmaxf(mx0, __shfl_xor_sync(0xffffffffu, mx0, 1));
        mx0 = fmaxf(mx0, __shfl_xor_sync(0xffffffffu, mx0, 2));
        mx1 = fmaxf(mx1, __shfl_xor_sync(0xffffffffu, mx1, 1));
        mx1 = fmaxf(mx1, __shfl_xor_sync(0xffffffffu, mx1, 2));

        float mn0 = fmaxf(m0r, mx0), mn1 = fmaxf(m1r, mx1);
        float cr0 = __expf(m0r - mn0), cr1 = __expf(m1r - mn1);
        float sum0 = 0.f, sum1 = 0.f;
#pragma unroll
        for (int j = 0; j < 16; j++) {
            sacc[j][0] = __expf(sacc[j][0] - mn0);
            sacc[j][1] = __expf(sacc[j][1] - mn0);
            sacc[j][2] = __expf(sacc[j][2] - mn1);
            sacc[j][3] = __expf(sacc[j][3] - mn1);
            sum0 += sacc[j][0] + sacc[j][1];
            sum1 += sacc[j][2] + sacc[j][3];
        }
        sum0 += __shfl_xor_sync(0xffffffffu, sum0, 1);
        sum0 += __shfl_xor_sync(0xffffffffu, sum0, 2);
        sum1 += __shfl_xor_sync(0xffffffffu, sum1, 1);
        sum1 += __shfl_xor_sync(0xffffffffu, sum1, 2);

        l0r = l0r * cr0 + sum0;  m0r = mn0;
        l1r = l1r * cr1 + sum1;  m1r = mn1;
#pragma unroll
        for (int j = 0; j < 8; j++) {
            oacc[j][0] *= cr0; oacc[j][1] *= cr0;
            oacc[j][2] *= cr1; oacc[j][3] *= cr1;
        }

        // ---- O += P V (P split hi/lo, from registers) ----
#pragma unroll
        for (int kt2 = 0; kt2 < 8; kt2++) {
            const int jA = 2 * kt2, jB = 2 * kt2 + 1;
            uint32_t ph[4], pl[4];
            ph[0] = pack_h2(sacc[jA][0], sacc[jA][1]);
            ph[1] = pack_h2(sacc[jA][2], sacc[jA][3]);
            ph[2] = pack_h2(sacc[jB][0], sacc[jB][1]);
            ph[3] = pack_h2(sacc[jB][2], sacc[jB][3]);
            {
                __half2 h0 = *(__half2*)&ph[0];
                __half2 h1 = *(__half2*)&ph[1];
                __half2 h2 = *(__half2*)&ph[2];
                __half2 h3 = *(__half2*)&ph[3];
                pl[0] = pack_h2(sacc[jA][0] - __low2float(h0), sacc[jA][1] - __high2float(h0));
                pl[1] = pack_h2(sacc[jA][2] - __low2float(h1), sacc[jA][3] - __high2float(h1));
                pl[2] = pack_h2(sacc[jB][0] - __low2float(h2), sacc[jB][1] - __high2float(h2));
                pl[3] = pack_h2(sacc[jB][2] - __low2float(h3), sacc[jB][3] - __high2float(h3));
            }
#pragma unroll
            for (int nt2 = 0; nt2 < 4; nt2++) {
                int r = nt2 * 16 + bRowBase;
                uint32_t vc = kt2 * 2 + bCsel;
                uint32_t bv[4];
                ldsm4(bv[0], bv[1], bv[2], bv[3], vb + swzV(r, vc));
                mma16816h(oacc[2*nt2],   ph[0], ph[1], ph[2], ph[3], bv[0], bv[1]);
                mma16816h(oacc[2*nt2+1], ph[0], ph[1], ph[2], ph[3], bv[2], bv[3]);
                mma16816h(oacc[2*nt2],   pl[0], pl[1], pl[2], pl[3], bv[0], bv[1]);
                mma16816h(oacc[2*nt2+1], pl[0], pl[1], pl[2], pl[3], bv[2], bv[3]);
            }
        }
    }

    // ---- normalize + store fp16 hi/lo split ----
    const float inv0 = 1.0f / l0r, inv1 = 1.0f / l1r;
    const size_t gr0 = (size_t)(b * SEQ + q0 + row0);
    const size_t gr1 = (size_t)(b * SEQ + q0 + row1);
#pragma unroll
    for (int nt = 0; nt < 8; nt++) {
        int col = h * D_HEAD + nt * 8 + qq * 2;
        float a0 = oacc[nt][0] * inv0, a1 = oacc[nt][1] * inv0;
        float b0f = oacc[nt][2] * inv1, b1f = oacc[nt][3] * inv1;
        uint32_t h0 = pack_h2(a0, a1), h1 = pack_h2(b0f, b1f);
        __half2 hh0 = *(__half2*)&h0, hh1 = *(__half2*)&h1;
        uint32_t l0 = pack_h2(a0 - __low2float(hh0), a1 - __high2float(hh0));
        uint32_t l1 = pack_h2(b0f - __low2float(hh1), b1f - __high2float(hh1));
        *(uint32_t*)(g_aoh + gr0 * K2 + col)           = h0;
        *(uint32_t*)(g_aoh + gr0 * K2 + D_MODEL + col) = l0;
        *(uint32_t*)(g_aoh + gr1 * K2 + col)           = h1;
        *(uint32_t*)(g_aoh + gr1 * K2 + D_MODEL + col) = l1;
    }
}

// ---------------------------------------------------------------------------
extern "C" void kernel_launch(void* const* d_in, const int* in_sizes, int n_in,
                              void* d_out, int out_size)
{
    const float* x  = (const float*)d_in[0];
    const float* Wq = (const float*)d_in[1];
    const float* Wk = (const float*)d_in[2];
    const float* Wv = (const float*)d_in[3];
    const float* Wo = (const float*)d_in[4];
    float* out = (float*)d_out;

    void *pqkv, *pxh, *paoh, *pwh;
    cudaGetSymbolAddress(&pqkv, g_qkv);
    cudaGetSymbolAddress(&pxh,  g_xh);
    cudaGetSymbolAddress(&paoh, g_aoh);
    cudaGetSymbolAddress(&pwh,  g_wh);

    __half* xh  = (__half*)pxh;
    __half* aoh = (__half*)paoh;
    __half* wh  = (__half*)pwh;

    cudaFuncSetAttribute(gemm_f16,
                         cudaFuncAttributeMaxDynamicSharedMemorySize, G_SMEM);
    cudaFuncSetAttribute(flash_attn_f16,
                         cudaFuncAttributeMaxDynamicSharedMemorySize, A_SMEM);

    const int n4x = M_ROWS * D_MODEL / 4;
    const int n4w = D_MODEL * D_MODEL / 4;
    const size_t WSZ = (size_t)D_MODEL * D_MODEL;

    split2<<<(n4x + 255) / 256, 256>>>(x, xh, n4x);
    convh4<<<dim3((n4w + 255) / 256, 4), 256>>>(Wq, Wk, Wv, Wo, wh, n4w);

    dim3 qkvgrid(K3 / BN, M_ROWS / BM);      // (24, 64)
    gemm_f16<<<qkvgrid, 256, G_SMEM>>>(xh, wh, (float*)pqkv, K3);

    dim3 pgrid(NQT, N_HEADS, B_SZ);          // (16, 16, 4)
    prep_attn<<<pgrid, 256>>>();

    dim3 fgrid(NQT, N_HEADS, B_SZ);
    flash_attn_f16<<<fgrid, 256, A_SMEM>>>();

    dim3 ogrid(D_MODEL / BN, M_ROWS / BM);   // (8, 64)
    gemm_f16<<<ogrid, 256, G_SMEM>>>(aoh, wh + 3 * WSZ, out, D_MODEL);
}